// round 13
// baseline (speedup 1.0000x reference)
#include <cuda_runtime.h>
#include <cuda_bf16.h>
#include <cuda_fp8.h>
#include <math.h>
#include <stdint.h>

#define NROWS 8192
#define DDIM  512
#define TS    128
#define NBLK  (NROWS / TS)        // 64
#define LDW   144                 // smem row stride: 128B data + 16B pad
#define GSTG  (2 * 128 * LDW)     // 36864 per stage
#define NSYM  (NBLK * (NBLK + 1) / 2)   // 2080
#define ZSTRIDE ((size_t)NROWS * DDIM)
#define FP8SCALE 16.0f

// ---------------- device scratch ----------------
__device__ __nv_bfloat16 g_Zb[2 * NROWS * DDIM];
__device__ __nv_bfloat16 g_Tb[2 * NROWS * DDIM];
__device__ __nv_bfloat16 g_Wb[2 * DDIM * DDIM];
__device__ float g_H [2 * NROWS * DDIM];
__device__ uint8_t g_F1[NROWS * DDIM];   // fp8 e4m3, scaled by 16
__device__ uint8_t g_F2[NROWS * DDIM];
__device__ float g_rs11p[NROWS * NBLK];
__device__ float g_rs22p[NROWS * NBLK];
__device__ float g_rs12p[NROWS * NBLK];
__device__ float g_cs12p[NROWS * NBLK];
__device__ float g_d12 [NROWS];
__device__ float g_loss[NROWS];

// ====================== helpers ======================
__device__ __forceinline__ uint32_t smem_u32(const void* p) {
    uint32_t a;
    asm("{ .reg .u64 t; cvta.to.shared.u64 t, %1; cvt.u32.u64 %0, t; }"
        : "=r"(a) : "l"(p));
    return a;
}
__device__ __forceinline__ void ldsm_x4(uint32_t (&r)[4], uint32_t addr) {
    asm volatile("ldmatrix.sync.aligned.m8n8.x4.shared.b16 {%0,%1,%2,%3}, [%4];"
        : "=r"(r[0]), "=r"(r[1]), "=r"(r[2]), "=r"(r[3]) : "r"(addr));
}
__device__ __forceinline__ void mma16816(float (&d)[4], const uint32_t (&a)[4],
                                         uint32_t b0, uint32_t b1) {
    asm volatile("mma.sync.aligned.m16n8k16.row.col.f32.bf16.bf16.f32 "
        "{%0,%1,%2,%3}, {%4,%5,%6,%7}, {%8,%9}, {%0,%1,%2,%3};"
        : "+f"(d[0]), "+f"(d[1]), "+f"(d[2]), "+f"(d[3])
        : "r"(a[0]), "r"(a[1]), "r"(a[2]), "r"(a[3]), "r"(b0), "r"(b1));
}
__device__ __forceinline__ void mma16832_fp8(float (&d)[4], const uint32_t (&a)[4],
                                             uint32_t b0, uint32_t b1) {
    asm volatile("mma.sync.aligned.m16n8k32.row.col.f32.e4m3.e4m3.f32 "
        "{%0,%1,%2,%3}, {%4,%5,%6,%7}, {%8,%9}, {%0,%1,%2,%3};"
        : "+f"(d[0]), "+f"(d[1]), "+f"(d[2]), "+f"(d[3])
        : "r"(a[0]), "r"(a[1]), "r"(a[2]), "r"(a[3]), "r"(b0), "r"(b1));
}
#define CP16(dst, src) \
    asm volatile("cp.async.cg.shared.global [%0], [%1], 16;" :: "r"(dst), "l"(src))
#define CPCOMMIT() asm volatile("cp.async.commit_group;" ::: "memory")
#define CPWAIT(n)  asm volatile("cp.async.wait_group %0;" :: "n"(n) : "memory")

__device__ __forceinline__ float fast_exp2(float x) {
    float y; asm("ex2.approx.f32 %0, %1;" : "=f"(y) : "f"(x)); return y;
}

// ============ fused convert: W1|W2|pri|aux -> bf16 in one launch ============
__global__ void __launch_bounds__(256)
convert_kernel(const float* __restrict__ W1, const float* __restrict__ W2,
               const float* __restrict__ pri, const float* __restrict__ aux,
               __nv_bfloat16* __restrict__ Wb, __nv_bfloat16* __restrict__ Zb) {
    const int b = blockIdx.x;
    const float* X;
    __nv_bfloat16* O;
    size_t base;
    if (b < 256)       { X = W1;  O = Wb;                          base = (size_t)b * 1024; }
    else if (b < 512)  { X = W2;  O = Wb + (size_t)DDIM * DDIM;    base = (size_t)(b - 256) * 1024; }
    else if (b < 4608) { X = pri; O = Zb;                          base = (size_t)(b - 512) * 1024; }
    else               { X = aux; O = Zb + ZSTRIDE;                base = (size_t)(b - 4608) * 1024; }
    const size_t i = base + (size_t)threadIdx.x * 4;
    float4 v = *(const float4*)(X + i);
    __nv_bfloat162 p0 = __floats2bfloat162_rn(v.x, v.y);
    __nv_bfloat162 p1 = __floats2bfloat162_rn(v.z, v.w);
    *(uint2*)(O + i) = make_uint2(*(uint32_t*)&p0, *(uint32_t*)&p1);
}

// ==== bf16 proj GEMM core: 128B K-chunks (8 chunks), 3-stage cp.async ======
__device__ __forceinline__ void gemm_tile_bf16w(const char* Ag, const char* Wg,
                                                uint32_t s0,
                                                float (&acc)[2][8][4],
                                                int tid, int lane, int warp_m, int warp_n) {
    const int q = lane >> 3, rr = lane & 7;
    const uint32_t lds_off = (uint32_t)(((q & 1) * 8 + rr) * LDW + (q >> 1) * 16);
    const uint32_t am_off = (uint32_t)(warp_m * 32) * LDW + lds_off;
    const uint32_t bn_off = 128u * LDW + (uint32_t)(warp_n * 64) * LDW + lds_off;

    auto load_chunk = [&](int kc, int stg) {
        const uint32_t b = s0 + stg * GSTG;
#pragma unroll
        for (int it = 0; it < 8; it++) {
            const int u = it * 256 + tid;
            const int m = u >> 10;
            const int row = (u >> 3) & 127;
            const int g = u & 7;
            const char* src = (m ? Wg : Ag) + (size_t)row * (DDIM * 2)
                              + (size_t)kc * 128 + g * 16;
            CP16(b + (uint32_t)m * (128u * LDW) + (uint32_t)row * LDW + g * 16, src);
        }
        CPCOMMIT();
    };

    load_chunk(0, 0);
    load_chunk(1, 1);
    int cur = 0;
    for (int kc = 0; kc < 8; kc++) {
        if (kc < 7) { CPWAIT(1); } else { CPWAIT(0); }
        __syncthreads();
        if (kc + 2 < 8) {
            int iss = cur + 2; if (iss >= 3) iss -= 3;
            load_chunk(kc + 2, iss);
        }
        const uint32_t b = s0 + cur * GSTG;
        const uint32_t a_base = b + am_off;
        const uint32_t b_base = b + bn_off;
#pragma unroll
        for (int kk = 0; kk < 4; kk++) {
            uint32_t af[2][4];
            ldsm_x4(af[0], a_base + kk * 32);
            ldsm_x4(af[1], a_base + 16 * LDW + kk * 32);
#pragma unroll
            for (int n2 = 0; n2 < 4; n2++) {
                uint32_t bf[4];
                ldsm_x4(bf, b_base + n2 * 16 * LDW + kk * 32);
#pragma unroll
                for (int mt = 0; mt < 2; mt++)
#pragma unroll
                    for (int u = 0; u < 2; u++)
                        mma16816(acc[mt][n2 * 2 + u], af[mt], bf[u], bf[u + 2]);
            }
        }
        cur = (cur + 1 == 3) ? 0 : cur + 1;
    }
    __syncthreads();
}

// ============ bf16 projection GEMM (single embedding per launch) ============
template <bool DO_ELU>
__global__ void __launch_bounds__(256, 2)
proj_kernel(const __nv_bfloat16* __restrict__ A, const __nv_bfloat16* __restrict__ W,
            const float* __restrict__ bias,
            float* __restrict__ Hout, __nv_bfloat16* __restrict__ Ob) {
    extern __shared__ __align__(128) char dynsm[];
    const int tid = threadIdx.x, lane = tid & 31, wid = tid >> 5;
    const int warp_m = wid & 3, warp_n = wid >> 2;
    const int cb = blockIdx.x, rb = blockIdx.y;

    float acc[2][8][4] = {};
    gemm_tile_bf16w((const char*)(A + (size_t)rb * TS * DDIM),
                    (const char*)(W + (size_t)cb * TS * DDIM),
                    smem_u32(dynsm), acc, tid, lane, warp_m, warp_n);

    const int cbase = cb * TS + warp_n * 64;
    const int rbase = rb * TS + warp_m * 32 + (lane >> 2);
#pragma unroll
    for (int mt = 0; mt < 2; mt++) {
        const int ra = rbase + mt * 16, rbb = ra + 8;
#pragma unroll
        for (int nt = 0; nt < 8; nt++) {
            const int c = cbase + nt * 8 + (lane & 3) * 2;
            const float bv0 = bias[c], bv1 = bias[c + 1];
            float x00 = acc[mt][nt][0] + bv0, x01 = acc[mt][nt][1] + bv1;
            float x10 = acc[mt][nt][2] + bv0, x11 = acc[mt][nt][3] + bv1;
            if (DO_ELU) {
                x00 = (x00 > 0.0f) ? x00 : expm1f(x00);
                x01 = (x01 > 0.0f) ? x01 : expm1f(x01);
                x10 = (x10 > 0.0f) ? x10 : expm1f(x10);
                x11 = (x11 > 0.0f) ? x11 : expm1f(x11);
                __nv_bfloat162 p = __floats2bfloat162_rn(x00, x01);
                __nv_bfloat162 q2 = __floats2bfloat162_rn(x10, x11);
                *(uint32_t*)(Ob + (size_t)ra  * DDIM + c) = *(uint32_t*)&p;
                *(uint32_t*)(Ob + (size_t)rbb * DDIM + c) = *(uint32_t*)&q2;
            } else {
                *(float2*)(Hout + (size_t)ra  * DDIM + c) = make_float2(x00, x01);
                *(float2*)(Hout + (size_t)rbb * DDIM + c) = make_float2(x10, x11);
            }
        }
    }
}

// ======= similarity tile core (fp8, 128B K-chunks, 3-stage cp.async) =======
__device__ __forceinline__ void sim_tile_mma_fp8(const char* Ag, const char* Bg,
                                                 uint32_t s0,
                                                 float (&acc)[2][8][4],
                                                 int tid, int lane, int warp_m, int warp_n) {
    const int q = lane >> 3, rr = lane & 7;
    const uint32_t lds_off = (uint32_t)(((q & 1) * 8 + rr) * LDW + (q >> 1) * 16);
    const uint32_t am_off = (uint32_t)(warp_m * 32) * LDW + lds_off;
    const uint32_t bn_off = 128u * LDW + (uint32_t)(warp_n * 64) * LDW + lds_off;

    auto load_chunk = [&](int kc, int stg) {
        const uint32_t b = s0 + stg * GSTG;
#pragma unroll
        for (int it = 0; it < 8; it++) {
            const int u = it * 256 + tid;
            const int m = u >> 10;
            const int row = (u >> 3) & 127;
            const int g = u & 7;
            const char* src = (m ? Bg : Ag) + (size_t)row * DDIM
                              + (size_t)kc * 128 + g * 16;
            CP16(b + (uint32_t)m * (128u * LDW) + (uint32_t)row * LDW + g * 16, src);
        }
        CPCOMMIT();
    };

    load_chunk(0, 0);
    load_chunk(1, 1);
    int cur = 0;
    for (int kc = 0; kc < 4; kc++) {
        if (kc < 3) { CPWAIT(1); } else { CPWAIT(0); }
        __syncthreads();
        if (kc + 2 < 4) {
            int iss = cur + 2; if (iss >= 3) iss -= 3;
            load_chunk(kc + 2, iss);
        }
        const uint32_t b = s0 + cur * GSTG;
        const uint32_t a_base = b + am_off;
        const uint32_t b_base = b + bn_off;
#pragma unroll
        for (int kk = 0; kk < 4; kk++) {
            uint32_t af[2][4];
            ldsm_x4(af[0], a_base + kk * 32);
            ldsm_x4(af[1], a_base + 16 * LDW + kk * 32);
#pragma unroll
            for (int n2 = 0; n2 < 4; n2++) {
                uint32_t bf[4];
                ldsm_x4(bf, b_base + n2 * 16 * LDW + kk * 32);
#pragma unroll
                for (int mt = 0; mt < 2; mt++)
#pragma unroll
                    for (int u = 0; u < 2; u++)
                        mma16832_fp8(acc[mt][n2 * 2 + u], af[mt], bf[u], bf[u + 2]);
            }
        }
        cur = (cur + 1 == 3) ? 0 : cur + 1;
    }
    __syncthreads();
}

// exp + row/col reductions (acc holds dot * 256)
__device__ __forceinline__ void sim_reduce(float (&acc)[2][8][4], char* sm,
                                           int lane, int warp_m, int warp_n,
                                           bool do_col) {
    float* rs_sm = (float*)sm;
    float* cs_sm = (float*)(sm + 1024);
    const float C = 2.8853900817779268f / (FP8SCALE * FP8SCALE);
    float rs_acc[2][2] = {};
    float cs2[8][2];
    if (do_col)
#pragma unroll
        for (int nt = 0; nt < 8; nt++) cs2[nt][0] = cs2[nt][1] = 0.0f;

#pragma unroll
    for (int mt = 0; mt < 2; mt++)
#pragma unroll
        for (int nt = 0; nt < 8; nt++) {
            float e0 = fast_exp2(acc[mt][nt][0] * C);
            float e1 = fast_exp2(acc[mt][nt][1] * C);
            float e2 = fast_exp2(acc[mt][nt][2] * C);
            float e3 = fast_exp2(acc[mt][nt][3] * C);
            rs_acc[mt][0] += e0 + e1;
            rs_acc[mt][1] += e2 + e3;
            if (do_col) { cs2[nt][0] += e0 + e2; cs2[nt][1] += e1 + e3; }
        }

#pragma unroll
    for (int mt = 0; mt < 2; mt++)
#pragma unroll
        for (int half = 0; half < 2; half++) {
            float v = rs_acc[mt][half];
            v += __shfl_xor_sync(0xffffffffu, v, 1);
            v += __shfl_xor_sync(0xffffffffu, v, 2);
            if ((lane & 3) == 0) {
                int row = warp_m * 32 + mt * 16 + half * 8 + (lane >> 2);
                rs_sm[row * 2 + warp_n] = v;
            }
        }
    if (do_col) {
#pragma unroll
        for (int nt = 0; nt < 8; nt++)
#pragma unroll
            for (int e = 0; e < 2; e++) {
                float v = cs2[nt][e];
                v += __shfl_xor_sync(0xffffffffu, v, 4);
                v += __shfl_xor_sync(0xffffffffu, v, 8);
                v += __shfl_xor_sync(0xffffffffu, v, 16);
                if (lane < 4) {
                    int col = warp_n * 64 + nt * 8 + lane * 2 + e;
                    cs_sm[warp_m * 128 + col] = v;
                }
            }
    }
    __syncthreads();
}

// ============== similarity kernel, partitioned for stream overlap ==========
// part 0: NSYM blocks — symmetric tiles of F1 -> rs11p
// part 1: NSYM + 4096 blocks — symmetric tiles of F2 -> rs22p, then cross -> rs12p/cs12p
__global__ void __launch_bounds__(256, 2)
sim_part_kernel(const uint8_t* __restrict__ F1, const uint8_t* __restrict__ F2,
                float* __restrict__ rs11p, float* __restrict__ rs22p,
                float* __restrict__ rs12p, float* __restrict__ cs12p,
                int part) {
    extern __shared__ __align__(128) char dynsm[];
    const int bid = blockIdx.x;
    const int tid = threadIdx.x, lane = tid & 31, wid = tid >> 5;
    const int warp_m = wid & 3, warp_n = wid >> 2;

    const uint8_t *A, *B;
    float *rsp, *csp;
    int rb, cb;
    bool diag = false, sym;

    if (part == 0 || bid < NSYM) {
        sym = true;
        const int idx = bid;
        int r = (int)(NBLK + 0.5f - sqrtf((NBLK + 0.5f) * (NBLK + 0.5f) - 2.0f * idx));
        if (r < 0) r = 0;
        if (r > NBLK - 1) r = NBLK - 1;
#define TRI_BASE(x) ((x) * NBLK - ((x) * ((x) - 1)) / 2)
        while (r + 1 <= NBLK - 1 && TRI_BASE(r + 1) <= idx) r++;
        while (r > 0 && TRI_BASE(r) > idx) r--;
        rb = r;
        cb = r + (idx - TRI_BASE(r));
#undef TRI_BASE
        A = (part == 0) ? F1 : F2;
        B = A;
        rsp = (part == 0) ? rs11p : rs22p;
        csp = nullptr;
        diag = (rb == cb);
    } else {
        sym = false;
        const int idx = bid - NSYM;
        rb = idx >> 6;
        cb = idx & (NBLK - 1);
        A = F1; B = F2;
        rsp = rs12p; csp = cs12p;
    }

    float acc[2][8][4] = {};
    sim_tile_mma_fp8((const char*)(A + (size_t)rb * TS * DDIM),
                     (const char*)(B + (size_t)cb * TS * DDIM),
                     smem_u32(dynsm), acc, tid, lane, warp_m, warp_n);
    sim_reduce(acc, dynsm, lane, warp_m, warp_n, !diag);

    float* rs_sm = (float*)dynsm;
    float* cs_sm = (float*)(dynsm + 1024);
    if (tid < TS) {
        rsp[(size_t)(rb * TS + tid) * NBLK + cb] = rs_sm[tid * 2] + rs_sm[tid * 2 + 1];
        if (!diag) {
            const float ctot = cs_sm[tid] + cs_sm[128 + tid] +
                               cs_sm[256 + tid] + cs_sm[384 + tid];
            if (sym) rsp[(size_t)(cb * TS + tid) * NBLK + rb] = ctot;
            else     csp[(size_t)(cb * TS + tid) * NBLK + rb] = ctot;
        }
    }
}

// -------- norm1: L2-normalize H1 -> fp8 F1 ----------------------------------
__global__ void __launch_bounds__(256)
norm1_kernel(const float* __restrict__ H, uint8_t* __restrict__ F1) {
    const int row  = blockIdx.x * 8 + (threadIdx.x >> 5);
    const int lane = threadIdx.x & 31;
    const float4* h1 = (const float4*)(H + (size_t)row * DDIM);
    float4 v1[4];
    float ss1 = 0.0f;
#pragma unroll
    for (int m = 0; m < 4; m++) {
        v1[m] = h1[lane + 32 * m];
        ss1 += v1[m].x * v1[m].x + v1[m].y * v1[m].y + v1[m].z * v1[m].z + v1[m].w * v1[m].w;
    }
#pragma unroll
    for (int o = 16; o > 0; o >>= 1) ss1 += __shfl_xor_sync(0xffffffffu, ss1, o);
    const float s1 = FP8SCALE / fmaxf(sqrtf(ss1), 1e-12f);
#pragma unroll
    for (int m = 0; m < 4; m++) {
        __nv_fp8x2_storage_t lo = __nv_cvt_float2_to_fp8x2(
            make_float2(v1[m].x * s1, v1[m].y * s1), __NV_SATFINITE, __NV_E4M3);
        __nv_fp8x2_storage_t hi = __nv_cvt_float2_to_fp8x2(
            make_float2(v1[m].z * s1, v1[m].w * s1), __NV_SATFINITE, __NV_E4M3);
        *(uint32_t*)(F1 + (size_t)row * DDIM + (lane + 32 * m) * 4) =
            (uint32_t)lo | ((uint32_t)hi << 16);
    }
}

// -------- norm2+d12: normalize H2 -> F2; d12 = <n1, n2> ---------------------
__global__ void __launch_bounds__(256)
norm2d12_kernel(const float* __restrict__ H, uint8_t* __restrict__ F2,
                float* __restrict__ d12) {
    const int row  = blockIdx.x * 8 + (threadIdx.x >> 5);
    const int lane = threadIdx.x & 31;
    const float4* h1 = (const float4*)(H + (size_t)row * DDIM);
    const float4* h2 = (const float4*)(H + ZSTRIDE + (size_t)row * DDIM);
    float4 v2[4];
    float ss1 = 0.0f, ss2 = 0.0f, dd = 0.0f;
#pragma unroll
    for (int m = 0; m < 4; m++) {
        float4 a = h1[lane + 32 * m];
        v2[m] = h2[lane + 32 * m];
        ss1 += a.x * a.x + a.y * a.y + a.z * a.z + a.w * a.w;
        ss2 += v2[m].x * v2[m].x + v2[m].y * v2[m].y + v2[m].z * v2[m].z + v2[m].w * v2[m].w;
        dd  += a.x * v2[m].x + a.y * v2[m].y + a.z * v2[m].z + a.w * v2[m].w;
    }
#pragma unroll
    for (int o = 16; o > 0; o >>= 1) {
        ss1 += __shfl_xor_sync(0xffffffffu, ss1, o);
        ss2 += __shfl_xor_sync(0xffffffffu, ss2, o);
        dd  += __shfl_xor_sync(0xffffffffu, dd,  o);
    }
    const float inv1 = 1.0f / fmaxf(sqrtf(ss1), 1e-12f);
    const float inv2 = 1.0f / fmaxf(sqrtf(ss2), 1e-12f);
    const float s2 = inv2 * FP8SCALE;
#pragma unroll
    for (int m = 0; m < 4; m++) {
        __nv_fp8x2_storage_t lo = __nv_cvt_float2_to_fp8x2(
            make_float2(v2[m].x * s2, v2[m].y * s2), __NV_SATFINITE, __NV_E4M3);
        __nv_fp8x2_storage_t hi = __nv_cvt_float2_to_fp8x2(
            make_float2(v2[m].z * s2, v2[m].w * s2), __NV_SATFINITE, __NV_E4M3);
        *(uint32_t*)(F2 + (size_t)row * DDIM + (lane + 32 * m) * 4) =
            (uint32_t)lo | ((uint32_t)hi << 16);
    }
    if (lane == 0) d12[row] = dd * inv1 * inv2;
}

__global__ void __launch_bounds__(256)
rowloss_kernel(const float* __restrict__ rs11p, const float* __restrict__ rs22p,
               const float* __restrict__ rs12p, const float* __restrict__ cs12p,
               const float* __restrict__ d12, float* __restrict__ loss) {
    const int row  = blockIdx.x * 8 + (threadIdx.x >> 5);
    const int lane = threadIdx.x & 31;
    float s11 = 0.0f, s22 = 0.0f, s12 = 0.0f, c12 = 0.0f;
    for (int m = lane; m < NBLK; m += 32) {
        const size_t o = (size_t)row * NBLK + m;
        s11 += rs11p[o];
        s22 += rs22p[o];
        s12 += rs12p[o];
        c12 += cs12p[o];
    }
#pragma unroll
    for (int o = 16; o > 0; o >>= 1) {
        s11 += __shfl_xor_sync(0xffffffffu, s11, o);
        s22 += __shfl_xor_sync(0xffffffffu, s22, o);
        s12 += __shfl_xor_sync(0xffffffffu, s12, o);
        c12 += __shfl_xor_sync(0xffffffffu, c12, o);
    }
    if (lane == 0) {
        const float E2 = 7.38905609893065f;   // exp(1/tau)
        const float den1 = s11 + s12 - E2;
        const float den2 = s22 + c12 - E2;
        loss[row] = -2.0f * d12[row] + 0.5f * (__logf(den1) + __logf(den2));
    }
}

__global__ void __launch_bounds__(1024)
final_kernel(const float* __restrict__ loss, float* __restrict__ out) {
    __shared__ float sm[1024];
    const int t = threadIdx.x;
    float s = 0.0f;
    for (int i = t; i < NROWS; i += 1024) s += loss[i];
    sm[t] = s;
    __syncthreads();
    for (int o = 512; o > 0; o >>= 1) {
        if (t < o) sm[t] += sm[t + o];
        __syncthreads();
    }
    if (t == 0) out[0] = sm[0] * (1.0f / NROWS);
}

// ---------------- launch ----------------------------------------------------
extern "C" void kernel_launch(void* const* d_in, const int* in_sizes, int n_in,
                              void* d_out, int out_size) {
    const float* pri = (const float*)d_in[0];
    const float* aux = (const float*)d_in[1];
    const float* W1  = (const float*)d_in[2];
    const float* b1  = (const float*)d_in[3];
    const float* W2  = (const float*)d_in[4];
    const float* b2  = (const float*)d_in[5];
    float* out = (float*)d_out;

    // one-time host resources for fork/join capture (host-side only; the
    // device work recorded into the graph is identical on every call)
    static cudaStream_t s1 = nullptr;
    static cudaEvent_t evFork = nullptr, evJoin = nullptr;
    if (s1 == nullptr) {
        cudaStreamCreateWithFlags(&s1, cudaStreamNonBlocking);
        cudaEventCreateWithFlags(&evFork, cudaEventDisableTiming);
        cudaEventCreateWithFlags(&evJoin, cudaEventDisableTiming);
    }

    __nv_bfloat16 *Zb, *Tb, *Wb;
    uint8_t *F1, *F2;
    float *H, *rs11p, *rs22p, *rs12p, *cs12p, *d12, *loss;
    cudaGetSymbolAddress((void**)&Zb,  g_Zb);
    cudaGetSymbolAddress((void**)&Tb,  g_Tb);
    cudaGetSymbolAddress((void**)&Wb,  g_Wb);
    cudaGetSymbolAddress((void**)&H,   g_H);
    cudaGetSymbolAddress((void**)&F1,  g_F1);
    cudaGetSymbolAddress((void**)&F2,  g_F2);
    cudaGetSymbolAddress((void**)&rs11p, g_rs11p);
    cudaGetSymbolAddress((void**)&rs22p, g_rs22p);
    cudaGetSymbolAddress((void**)&rs12p, g_rs12p);
    cudaGetSymbolAddress((void**)&cs12p, g_cs12p);
    cudaGetSymbolAddress((void**)&d12,  g_d12);
    cudaGetSymbolAddress((void**)&loss, g_loss);

    const int gemmSmem = 3 * GSTG;   // 110592
    cudaFuncSetAttribute(proj_kernel<true >,
                         cudaFuncAttributeMaxDynamicSharedMemorySize, gemmSmem);
    cudaFuncSetAttribute(proj_kernel<false>,
                         cudaFuncAttributeMaxDynamicSharedMemorySize, gemmSmem);
    cudaFuncSetAttribute(sim_part_kernel,
                         cudaFuncAttributeMaxDynamicSharedMemorySize, gemmSmem);

    const dim3 pg(DDIM / TS, NROWS / TS);           // (4, 64)
    const int cvtBlocks = 512 + 2 * (NROWS * DDIM / 1024);   // 8704
    __nv_bfloat16* W2b = Wb + (size_t)DDIM * DDIM;

    convert_kernel<<<cvtBlocks, 256>>>(W1, W2, pri, aux, Wb, Zb);

    // ---- pri chain ----
    proj_kernel<true ><<<pg, 256, gemmSmem>>>(Zb, Wb, b1, nullptr, Tb);
    proj_kernel<false><<<pg, 256, gemmSmem>>>(Tb, W2b, b2, H, nullptr);
    norm1_kernel<<<NROWS / 8, 256>>>(H, F1);

    // ---- fork: S11 tiles on s1 while aux chain runs on default stream ----
    cudaEventRecord(evFork, 0);
    cudaStreamWaitEvent(s1, evFork, 0);
    sim_part_kernel<<<NSYM, 256, gemmSmem, s1>>>(F1, F1, rs11p, rs22p,
                                                 rs12p, cs12p, 0);
    cudaEventRecord(evJoin, s1);

    // ---- aux chain on default stream ----
    proj_kernel<true ><<<pg, 256, gemmSmem>>>(Zb + ZSTRIDE, Wb, b1, nullptr,
                                              Tb + ZSTRIDE);
    proj_kernel<false><<<pg, 256, gemmSmem>>>(Tb + ZSTRIDE, W2b, b2,
                                              H + ZSTRIDE, nullptr);
    norm2d12_kernel<<<NROWS / 8, 256>>>(H, F2, d12);

    // ---- join, then the remaining sim tiles (S22 sym + S12 cross) ----
    cudaStreamWaitEvent(0, evJoin, 0);
    sim_part_kernel<<<NSYM + NBLK * NBLK, 256, gemmSmem>>>(F1, F2, rs11p, rs22p,
                                                           rs12p, cs12p, 1);

    rowloss_kernel<<<NROWS / 8, 256>>>(rs11p, rs22p, rs12p, cs12p, d12, loss);
    final_kernel<<<1, 1024>>>(loss, out);
}

// round 14
// speedup vs baseline: 1.0172x; 1.0172x over previous
#include <cuda_runtime.h>
#include <cuda_bf16.h>
#include <cuda_fp8.h>
#include <math.h>
#include <stdint.h>

#define NROWS 8192
#define DDIM  512
#define TS    128
#define NBLK  (NROWS / TS)        // 64
#define LDW   144                 // smem row stride: 128B data + 16B pad
#define GSTG  (2 * 128 * LDW)     // 36864 per stage
#define NSYM  (NBLK * (NBLK + 1) / 2)   // 2080
#define ZSTRIDE ((size_t)NROWS * DDIM)
#define FP8SCALE 16.0f

// ---------------- device scratch ----------------
__device__ __nv_bfloat16 g_Zb[2 * NROWS * DDIM];
__device__ __nv_bfloat16 g_Tb[2 * NROWS * DDIM];
__device__ __nv_bfloat16 g_Wb[2 * DDIM * DDIM];
__device__ __nv_bfloat16 g_Hb[2 * NROWS * DDIM];   // layer-2 out, bf16
__device__ uint8_t g_F1[NROWS * DDIM];   // fp8 e4m3, scaled by 16
__device__ uint8_t g_F2[NROWS * DDIM];
__device__ float g_rs11p[NROWS * NBLK];
__device__ float g_rs22p[NROWS * NBLK];
__device__ float g_rs12p[NROWS * NBLK];
__device__ float g_cs12p[NROWS * NBLK];
__device__ float g_d12 [NROWS];
__device__ float g_loss[NROWS];

// ====================== helpers ======================
__device__ __forceinline__ uint32_t smem_u32(const void* p) {
    uint32_t a;
    asm("{ .reg .u64 t; cvta.to.shared.u64 t, %1; cvt.u32.u64 %0, t; }"
        : "=r"(a) : "l"(p));
    return a;
}
__device__ __forceinline__ void ldsm_x4(uint32_t (&r)[4], uint32_t addr) {
    asm volatile("ldmatrix.sync.aligned.m8n8.x4.shared.b16 {%0,%1,%2,%3}, [%4];"
        : "=r"(r[0]), "=r"(r[1]), "=r"(r[2]), "=r"(r[3]) : "r"(addr));
}
__device__ __forceinline__ void mma16816(float (&d)[4], const uint32_t (&a)[4],
                                         uint32_t b0, uint32_t b1) {
    asm volatile("mma.sync.aligned.m16n8k16.row.col.f32.bf16.bf16.f32 "
        "{%0,%1,%2,%3}, {%4,%5,%6,%7}, {%8,%9}, {%0,%1,%2,%3};"
        : "+f"(d[0]), "+f"(d[1]), "+f"(d[2]), "+f"(d[3])
        : "r"(a[0]), "r"(a[1]), "r"(a[2]), "r"(a[3]), "r"(b0), "r"(b1));
}
__device__ __forceinline__ void mma16832_fp8(float (&d)[4], const uint32_t (&a)[4],
                                             uint32_t b0, uint32_t b1) {
    asm volatile("mma.sync.aligned.m16n8k32.row.col.f32.e4m3.e4m3.f32 "
        "{%0,%1,%2,%3}, {%4,%5,%6,%7}, {%8,%9}, {%0,%1,%2,%3};"
        : "+f"(d[0]), "+f"(d[1]), "+f"(d[2]), "+f"(d[3])
        : "r"(a[0]), "r"(a[1]), "r"(a[2]), "r"(a[3]), "r"(b0), "r"(b1));
}
#define CP16(dst, src) \
    asm volatile("cp.async.cg.shared.global [%0], [%1], 16;" :: "r"(dst), "l"(src))
#define CPCOMMIT() asm volatile("cp.async.commit_group;" ::: "memory")
#define CPWAIT(n)  asm volatile("cp.async.wait_group %0;" :: "n"(n) : "memory")

__device__ __forceinline__ float fast_exp2(float x) {
    float y; asm("ex2.approx.f32 %0, %1;" : "=f"(y) : "f"(x)); return y;
}
__device__ __forceinline__ float2 bf2f(uint32_t u) {
    __nv_bfloat162 b = *(__nv_bfloat162*)&u;
    return make_float2(__bfloat162float(b.x), __bfloat162float(b.y));
}

// ============ fused convert: W1|W2|pri|aux -> bf16 in one launch ============
__global__ void __launch_bounds__(256)
convert_kernel(const float* __restrict__ W1, const float* __restrict__ W2,
               const float* __restrict__ pri, const float* __restrict__ aux,
               __nv_bfloat16* __restrict__ Wb, __nv_bfloat16* __restrict__ Zb) {
    const int b = blockIdx.x;
    const float* X;
    __nv_bfloat16* O;
    size_t base;
    if (b < 256)       { X = W1;  O = Wb;                          base = (size_t)b * 1024; }
    else if (b < 512)  { X = W2;  O = Wb + (size_t)DDIM * DDIM;    base = (size_t)(b - 256) * 1024; }
    else if (b < 4608) { X = pri; O = Zb;                          base = (size_t)(b - 512) * 1024; }
    else               { X = aux; O = Zb + ZSTRIDE;                base = (size_t)(b - 4608) * 1024; }
    const size_t i = base + (size_t)threadIdx.x * 4;
    float4 v = *(const float4*)(X + i);
    __nv_bfloat162 p0 = __floats2bfloat162_rn(v.x, v.y);
    __nv_bfloat162 p1 = __floats2bfloat162_rn(v.z, v.w);
    *(uint2*)(O + i) = make_uint2(*(uint32_t*)&p0, *(uint32_t*)&p1);
}

// ==== bf16 proj GEMM core: 128B K-chunks (8 chunks), 3-stage cp.async ======
__device__ __forceinline__ void gemm_tile_bf16w(const char* Ag, const char* Wg,
                                                uint32_t s0,
                                                float (&acc)[2][8][4],
                                                int tid, int lane, int warp_m, int warp_n) {
    const int q = lane >> 3, rr = lane & 7;
    const uint32_t lds_off = (uint32_t)(((q & 1) * 8 + rr) * LDW + (q >> 1) * 16);
    const uint32_t am_off = (uint32_t)(warp_m * 32) * LDW + lds_off;
    const uint32_t bn_off = 128u * LDW + (uint32_t)(warp_n * 64) * LDW + lds_off;

    auto load_chunk = [&](int kc, int stg) {
        const uint32_t b = s0 + stg * GSTG;
#pragma unroll
        for (int it = 0; it < 8; it++) {
            const int u = it * 256 + tid;
            const int m = u >> 10;
            const int row = (u >> 3) & 127;
            const int g = u & 7;
            const char* src = (m ? Wg : Ag) + (size_t)row * (DDIM * 2)
                              + (size_t)kc * 128 + g * 16;
            CP16(b + (uint32_t)m * (128u * LDW) + (uint32_t)row * LDW + g * 16, src);
        }
        CPCOMMIT();
    };

    load_chunk(0, 0);
    load_chunk(1, 1);
    int cur = 0;
    for (int kc = 0; kc < 8; kc++) {
        if (kc < 7) { CPWAIT(1); } else { CPWAIT(0); }
        __syncthreads();
        if (kc + 2 < 8) {
            int iss = cur + 2; if (iss >= 3) iss -= 3;
            load_chunk(kc + 2, iss);
        }
        const uint32_t b = s0 + cur * GSTG;
        const uint32_t a_base = b + am_off;
        const uint32_t b_base = b + bn_off;
#pragma unroll
        for (int kk = 0; kk < 4; kk++) {
            uint32_t af[2][4];
            ldsm_x4(af[0], a_base + kk * 32);
            ldsm_x4(af[1], a_base + 16 * LDW + kk * 32);
#pragma unroll
            for (int n2 = 0; n2 < 4; n2++) {
                uint32_t bf[4];
                ldsm_x4(bf, b_base + n2 * 16 * LDW + kk * 32);
#pragma unroll
                for (int mt = 0; mt < 2; mt++)
#pragma unroll
                    for (int u = 0; u < 2; u++)
                        mma16816(acc[mt][n2 * 2 + u], af[mt], bf[u], bf[u + 2]);
            }
        }
        cur = (cur + 1 == 3) ? 0 : cur + 1;
    }
    __syncthreads();
}

// ============ bf16 projection GEMM (z-batched over embeddings) ==============
// OUT = act(A @ W^T + b), written as bf16.
template <bool DO_ELU>
__global__ void __launch_bounds__(256, 2)
proj_kernel(const __nv_bfloat16* __restrict__ A, const __nv_bfloat16* __restrict__ W,
            const float* __restrict__ bias, __nv_bfloat16* __restrict__ Ob) {
    extern __shared__ __align__(128) char dynsm[];
    const int tid = threadIdx.x, lane = tid & 31, wid = tid >> 5;
    const int warp_m = wid & 3, warp_n = wid >> 2;
    const int cb = blockIdx.x, rb = blockIdx.y;
    const size_t zoff = (size_t)blockIdx.z * ZSTRIDE;

    float acc[2][8][4] = {};
    gemm_tile_bf16w((const char*)(A + zoff + (size_t)rb * TS * DDIM),
                    (const char*)(W + (size_t)cb * TS * DDIM),
                    smem_u32(dynsm), acc, tid, lane, warp_m, warp_n);

    const int cbase = cb * TS + warp_n * 64;
    const int rbase = rb * TS + warp_m * 32 + (lane >> 2);
#pragma unroll
    for (int mt = 0; mt < 2; mt++) {
        const int ra = rbase + mt * 16, rbb = ra + 8;
#pragma unroll
        for (int nt = 0; nt < 8; nt++) {
            const int c = cbase + nt * 8 + (lane & 3) * 2;
            const float bv0 = bias[c], bv1 = bias[c + 1];
            float x00 = acc[mt][nt][0] + bv0, x01 = acc[mt][nt][1] + bv1;
            float x10 = acc[mt][nt][2] + bv0, x11 = acc[mt][nt][3] + bv1;
            if (DO_ELU) {
                x00 = (x00 > 0.0f) ? x00 : expm1f(x00);
                x01 = (x01 > 0.0f) ? x01 : expm1f(x01);
                x10 = (x10 > 0.0f) ? x10 : expm1f(x10);
                x11 = (x11 > 0.0f) ? x11 : expm1f(x11);
            }
            __nv_bfloat162 p = __floats2bfloat162_rn(x00, x01);
            __nv_bfloat162 q2 = __floats2bfloat162_rn(x10, x11);
            *(uint32_t*)(Ob + zoff + (size_t)ra  * DDIM + c) = *(uint32_t*)&p;
            *(uint32_t*)(Ob + zoff + (size_t)rbb * DDIM + c) = *(uint32_t*)&q2;
        }
    }
}

// ======= similarity tile core (fp8, 128B K-chunks, 3-stage cp.async) =======
__device__ __forceinline__ void sim_tile_mma_fp8(const char* Ag, const char* Bg,
                                                 uint32_t s0,
                                                 float (&acc)[2][8][4],
                                                 int tid, int lane, int warp_m, int warp_n) {
    const int q = lane >> 3, rr = lane & 7;
    const uint32_t lds_off = (uint32_t)(((q & 1) * 8 + rr) * LDW + (q >> 1) * 16);
    const uint32_t am_off = (uint32_t)(warp_m * 32) * LDW + lds_off;
    const uint32_t bn_off = 128u * LDW + (uint32_t)(warp_n * 64) * LDW + lds_off;

    auto load_chunk = [&](int kc, int stg) {
        const uint32_t b = s0 + stg * GSTG;
#pragma unroll
        for (int it = 0; it < 8; it++) {
            const int u = it * 256 + tid;
            const int m = u >> 10;
            const int row = (u >> 3) & 127;
            const int g = u & 7;
            const char* src = (m ? Bg : Ag) + (size_t)row * DDIM
                              + (size_t)kc * 128 + g * 16;
            CP16(b + (uint32_t)m * (128u * LDW) + (uint32_t)row * LDW + g * 16, src);
        }
        CPCOMMIT();
    };

    load_chunk(0, 0);
    load_chunk(1, 1);
    int cur = 0;
    for (int kc = 0; kc < 4; kc++) {
        if (kc < 3) { CPWAIT(1); } else { CPWAIT(0); }
        __syncthreads();
        if (kc + 2 < 4) {
            int iss = cur + 2; if (iss >= 3) iss -= 3;
            load_chunk(kc + 2, iss);
        }
        const uint32_t b = s0 + cur * GSTG;
        const uint32_t a_base = b + am_off;
        const uint32_t b_base = b + bn_off;
#pragma unroll
        for (int kk = 0; kk < 4; kk++) {
            uint32_t af[2][4];
            ldsm_x4(af[0], a_base + kk * 32);
            ldsm_x4(af[1], a_base + 16 * LDW + kk * 32);
#pragma unroll
            for (int n2 = 0; n2 < 4; n2++) {
                uint32_t bf[4];
                ldsm_x4(bf, b_base + n2 * 16 * LDW + kk * 32);
#pragma unroll
                for (int mt = 0; mt < 2; mt++)
#pragma unroll
                    for (int u = 0; u < 2; u++)
                        mma16832_fp8(acc[mt][n2 * 2 + u], af[mt], bf[u], bf[u + 2]);
            }
        }
        cur = (cur + 1 == 3) ? 0 : cur + 1;
    }
    __syncthreads();
}

// exp + row/col reductions (acc holds dot * 256)
__device__ __forceinline__ void sim_reduce(float (&acc)[2][8][4], char* sm,
                                           int lane, int warp_m, int warp_n,
                                           bool do_col) {
    float* rs_sm = (float*)sm;
    float* cs_sm = (float*)(sm + 1024);
    const float C = 2.8853900817779268f / (FP8SCALE * FP8SCALE);
    float rs_acc[2][2] = {};
    float cs2[8][2];
    if (do_col)
#pragma unroll
        for (int nt = 0; nt < 8; nt++) cs2[nt][0] = cs2[nt][1] = 0.0f;

#pragma unroll
    for (int mt = 0; mt < 2; mt++)
#pragma unroll
        for (int nt = 0; nt < 8; nt++) {
            float e0 = fast_exp2(acc[mt][nt][0] * C);
            float e1 = fast_exp2(acc[mt][nt][1] * C);
            float e2 = fast_exp2(acc[mt][nt][2] * C);
            float e3 = fast_exp2(acc[mt][nt][3] * C);
            rs_acc[mt][0] += e0 + e1;
            rs_acc[mt][1] += e2 + e3;
            if (do_col) { cs2[nt][0] += e0 + e2; cs2[nt][1] += e1 + e3; }
        }

#pragma unroll
    for (int mt = 0; mt < 2; mt++)
#pragma unroll
        for (int half = 0; half < 2; half++) {
            float v = rs_acc[mt][half];
            v += __shfl_xor_sync(0xffffffffu, v, 1);
            v += __shfl_xor_sync(0xffffffffu, v, 2);
            if ((lane & 3) == 0) {
                int row = warp_m * 32 + mt * 16 + half * 8 + (lane >> 2);
                rs_sm[row * 2 + warp_n] = v;
            }
        }
    if (do_col) {
#pragma unroll
        for (int nt = 0; nt < 8; nt++)
#pragma unroll
            for (int e = 0; e < 2; e++) {
                float v = cs2[nt][e];
                v += __shfl_xor_sync(0xffffffffu, v, 4);
                v += __shfl_xor_sync(0xffffffffu, v, 8);
                v += __shfl_xor_sync(0xffffffffu, v, 16);
                if (lane < 4) {
                    int col = warp_n * 64 + nt * 8 + lane * 2 + e;
                    cs_sm[warp_m * 128 + col] = v;
                }
            }
    }
    __syncthreads();
}

// ============ unified similarity kernel: all 8256 tiles in ONE launch =======
__global__ void __launch_bounds__(256, 2)
sim_all_kernel(const uint8_t* __restrict__ F1, const uint8_t* __restrict__ F2,
               float* __restrict__ rs11p, float* __restrict__ rs22p,
               float* __restrict__ rs12p, float* __restrict__ cs12p) {
    extern __shared__ __align__(128) char dynsm[];
    const int bid = blockIdx.x;
    const int tid = threadIdx.x, lane = tid & 31, wid = tid >> 5;
    const int warp_m = wid & 3, warp_n = wid >> 2;

    const uint8_t *A, *B;
    float *rsp, *csp;
    int rb, cb;
    bool diag = false, sym;

    if (bid < 2 * NSYM) {
        sym = true;
        const int z = (bid >= NSYM) ? 1 : 0;
        const int idx = bid - z * NSYM;
        int r = (int)(NBLK + 0.5f - sqrtf((NBLK + 0.5f) * (NBLK + 0.5f) - 2.0f * idx));
        if (r < 0) r = 0;
        if (r > NBLK - 1) r = NBLK - 1;
#define TRI_BASE(x) ((x) * NBLK - ((x) * ((x) - 1)) / 2)
        while (r + 1 <= NBLK - 1 && TRI_BASE(r + 1) <= idx) r++;
        while (r > 0 && TRI_BASE(r) > idx) r--;
        rb = r;
        cb = r + (idx - TRI_BASE(r));
#undef TRI_BASE
        A = z ? F2 : F1;
        B = A;
        rsp = z ? rs22p : rs11p;
        csp = nullptr;
        diag = (rb == cb);
    } else {
        sym = false;
        const int idx = bid - 2 * NSYM;
        rb = idx >> 6;
        cb = idx & (NBLK - 1);
        A = F1; B = F2;
        rsp = rs12p; csp = cs12p;
    }

    float acc[2][8][4] = {};
    sim_tile_mma_fp8((const char*)(A + (size_t)rb * TS * DDIM),
                     (const char*)(B + (size_t)cb * TS * DDIM),
                     smem_u32(dynsm), acc, tid, lane, warp_m, warp_n);
    sim_reduce(acc, dynsm, lane, warp_m, warp_n, !diag);

    float* rs_sm = (float*)dynsm;
    float* cs_sm = (float*)(dynsm + 1024);
    if (tid < TS) {
        rsp[(size_t)(rb * TS + tid) * NBLK + cb] = rs_sm[tid * 2] + rs_sm[tid * 2 + 1];
        if (!diag) {
            const float ctot = cs_sm[tid] + cs_sm[128 + tid] +
                               cs_sm[256 + tid] + cs_sm[384 + tid];
            if (sym) rsp[(size_t)(cb * TS + tid) * NBLK + rb] = ctot;
            else     csp[(size_t)(cb * TS + tid) * NBLK + rb] = ctot;
        }
    }
}

// ------- fused: L2-normalize both embeddings (bf16 in), d12, fp8 out -------
__global__ void __launch_bounds__(256)
normd12_kernel(const __nv_bfloat16* __restrict__ Hb, uint8_t* __restrict__ F1,
               uint8_t* __restrict__ F2, float* __restrict__ d12) {
    const int row  = blockIdx.x * 8 + (threadIdx.x >> 5);
    const int lane = threadIdx.x & 31;
    const uint4* h1 = (const uint4*)(Hb + (size_t)row * DDIM);
    const uint4* h2 = (const uint4*)(Hb + ZSTRIDE + (size_t)row * DDIM);
    float a1[16], a2[16];
    float ss1 = 0.0f, ss2 = 0.0f, dd = 0.0f;
#pragma unroll
    for (int m = 0; m < 2; m++) {
        uint4 u = h1[lane + 32 * m];
        uint4 w = h2[lane + 32 * m];
        const uint32_t up[4] = {u.x, u.y, u.z, u.w};
        const uint32_t wp[4] = {w.x, w.y, w.z, w.w};
#pragma unroll
        for (int k = 0; k < 4; k++) {
            float2 f1 = bf2f(up[k]);
            float2 f2 = bf2f(wp[k]);
            a1[m * 8 + k * 2]     = f1.x;
            a1[m * 8 + k * 2 + 1] = f1.y;
            a2[m * 8 + k * 2]     = f2.x;
            a2[m * 8 + k * 2 + 1] = f2.y;
            ss1 += f1.x * f1.x + f1.y * f1.y;
            ss2 += f2.x * f2.x + f2.y * f2.y;
            dd  += f1.x * f2.x + f1.y * f2.y;
        }
    }
#pragma unroll
    for (int o = 16; o > 0; o >>= 1) {
        ss1 += __shfl_xor_sync(0xffffffffu, ss1, o);
        ss2 += __shfl_xor_sync(0xffffffffu, ss2, o);
        dd  += __shfl_xor_sync(0xffffffffu, dd,  o);
    }
    const float inv1 = 1.0f / fmaxf(sqrtf(ss1), 1e-12f);
    const float inv2 = 1.0f / fmaxf(sqrtf(ss2), 1e-12f);
    const float s1 = inv1 * FP8SCALE, s2 = inv2 * FP8SCALE;
#pragma unroll
    for (int m = 0; m < 2; m++)
#pragma unroll
        for (int k = 0; k < 2; k++) {
            const int e = m * 8 + k * 4;
            __nv_fp8x2_storage_t lo1 = __nv_cvt_float2_to_fp8x2(
                make_float2(a1[e] * s1, a1[e + 1] * s1), __NV_SATFINITE, __NV_E4M3);
            __nv_fp8x2_storage_t hi1 = __nv_cvt_float2_to_fp8x2(
                make_float2(a1[e + 2] * s1, a1[e + 3] * s1), __NV_SATFINITE, __NV_E4M3);
            *(uint32_t*)(F1 + (size_t)row * DDIM + (lane + 32 * m) * 8 + k * 4) =
                (uint32_t)lo1 | ((uint32_t)hi1 << 16);
            __nv_fp8x2_storage_t lo2 = __nv_cvt_float2_to_fp8x2(
                make_float2(a2[e] * s2, a2[e + 1] * s2), __NV_SATFINITE, __NV_E4M3);
            __nv_fp8x2_storage_t hi2 = __nv_cvt_float2_to_fp8x2(
                make_float2(a2[e + 2] * s2, a2[e + 3] * s2), __NV_SATFINITE, __NV_E4M3);
            *(uint32_t*)(F2 + (size_t)row * DDIM + (lane + 32 * m) * 8 + k * 4) =
                (uint32_t)lo2 | ((uint32_t)hi2 << 16);
        }
    if (lane == 0) d12[row] = dd * inv1 * inv2;
}

__global__ void __launch_bounds__(256)
rowloss_kernel(const float* __restrict__ rs11p, const float* __restrict__ rs22p,
               const float* __restrict__ rs12p, const float* __restrict__ cs12p,
               const float* __restrict__ d12, float* __restrict__ loss) {
    const int row  = blockIdx.x * 8 + (threadIdx.x >> 5);
    const int lane = threadIdx.x & 31;
    float s11 = 0.0f, s22 = 0.0f, s12 = 0.0f, c12 = 0.0f;
    for (int m = lane; m < NBLK; m += 32) {
        const size_t o = (size_t)row * NBLK + m;
        s11 += rs11p[o];
        s22 += rs22p[o];
        s12 += rs12p[o];
        c12 += cs12p[o];
    }
#pragma unroll
    for (int o = 16; o > 0; o >>= 1) {
        s11 += __shfl_xor_sync(0xffffffffu, s11, o);
        s22 += __shfl_xor_sync(0xffffffffu, s22, o);
        s12 += __shfl_xor_sync(0xffffffffu, s12, o);
        c12 += __shfl_xor_sync(0xffffffffu, c12, o);
    }
    if (lane == 0) {
        const float E2 = 7.38905609893065f;   // exp(1/tau)
        const float den1 = s11 + s12 - E2;
        const float den2 = s22 + c12 - E2;
        loss[row] = -2.0f * d12[row] + 0.5f * (__logf(den1) + __logf(den2));
    }
}

__global__ void __launch_bounds__(1024)
final_kernel(const float* __restrict__ loss, float* __restrict__ out) {
    __shared__ float sm[1024];
    const int t = threadIdx.x;
    float s = 0.0f;
    for (int i = t; i < NROWS; i += 1024) s += loss[i];
    sm[t] = s;
    __syncthreads();
    for (int o = 512; o > 0; o >>= 1) {
        if (t < o) sm[t] += sm[t + o];
        __syncthreads();
    }
    if (t == 0) out[0] = sm[0] * (1.0f / NROWS);
}

// ---------------- launch ----------------------------------------------------
extern "C" void kernel_launch(void* const* d_in, const int* in_sizes, int n_in,
                              void* d_out, int out_size) {
    const float* pri = (const float*)d_in[0];
    const float* aux = (const float*)d_in[1];
    const float* W1  = (const float*)d_in[2];
    const float* b1  = (const float*)d_in[3];
    const float* W2  = (const float*)d_in[4];
    const float* b2  = (const float*)d_in[5];
    float* out = (float*)d_out;

    __nv_bfloat16 *Zb, *Tb, *Wb, *Hb;
    uint8_t *F1, *F2;
    float *rs11p, *rs22p, *rs12p, *cs12p, *d12, *loss;
    cudaGetSymbolAddress((void**)&Zb,  g_Zb);
    cudaGetSymbolAddress((void**)&Tb,  g_Tb);
    cudaGetSymbolAddress((void**)&Wb,  g_Wb);
    cudaGetSymbolAddress((void**)&Hb,  g_Hb);
    cudaGetSymbolAddress((void**)&F1,  g_F1);
    cudaGetSymbolAddress((void**)&F2,  g_F2);
    cudaGetSymbolAddress((void**)&rs11p, g_rs11p);
    cudaGetSymbolAddress((void**)&rs22p, g_rs22p);
    cudaGetSymbolAddress((void**)&rs12p, g_rs12p);
    cudaGetSymbolAddress((void**)&cs12p, g_cs12p);
    cudaGetSymbolAddress((void**)&d12,  g_d12);
    cudaGetSymbolAddress((void**)&loss, g_loss);

    const int gemmSmem = 3 * GSTG;   // 110592
    cudaFuncSetAttribute(proj_kernel<true >,
                         cudaFuncAttributeMaxDynamicSharedMemorySize, gemmSmem);
    cudaFuncSetAttribute(proj_kernel<false>,
                         cudaFuncAttributeMaxDynamicSharedMemorySize, gemmSmem);
    cudaFuncSetAttribute(sim_all_kernel,
                         cudaFuncAttributeMaxDynamicSharedMemorySize, gemmSmem);

    const dim3 pg(DDIM / TS, NROWS / TS, 2);        // (4, 64, 2)
    const int simBlocks = 2 * NSYM + NBLK * NBLK;   // 8256
    const int cvtBlocks = 512 + 2 * (NROWS * DDIM / 1024);   // 8704

    convert_kernel<<<cvtBlocks, 256>>>(W1, W2, pri, aux, Wb, Zb);

    proj_kernel<true ><<<pg, 256, gemmSmem>>>(Zb, Wb, b1, Tb);
    proj_kernel<false><<<pg, 256, gemmSmem>>>(Tb, Wb + (size_t)DDIM * DDIM, b2, Hb);

    normd12_kernel<<<NROWS / 8, 256>>>(Hb, F1, F2, d12);

    sim_all_kernel<<<simBlocks, 256, gemmSmem>>>(F1, F2, rs11p, rs22p, rs12p, cs12p);

    rowloss_kernel<<<NROWS / 8, 256>>>(rs11p, rs22p, rs12p, cs12p, d12, loss);
    final_kernel<<<1, 1024>>>(loss, out);
}

// round 15
// speedup vs baseline: 1.0856x; 1.0672x over previous
#include <cuda_runtime.h>
#include <cuda_bf16.h>
#include <cuda_fp16.h>
#include <cuda_fp8.h>
#include <math.h>
#include <stdint.h>

#define NROWS 8192
#define DDIM  512
#define TS    128
#define NBLK  (NROWS / TS)        // 64
#define LDW   144                 // smem row stride: 128B data + 16B pad
#define GSTG  (2 * 128 * LDW)     // 36864 per stage
#define NSYM  (NBLK * (NBLK + 1) / 2)   // 2080
#define ZSTRIDE ((size_t)NROWS * DDIM)
#define FP8SCALE 16.0f

// ---------------- device scratch ----------------
__device__ __nv_bfloat16 g_Zb[2 * NROWS * DDIM];
__device__ __nv_bfloat16 g_Tb[2 * NROWS * DDIM];
__device__ __nv_bfloat16 g_Wb[2 * DDIM * DDIM];
__device__ __nv_bfloat16 g_Hb[2 * NROWS * DDIM];   // layer-2 out, bf16
__device__ uint8_t g_F1[NROWS * DDIM];   // fp8 e4m3, scaled by 16
__device__ uint8_t g_F2[NROWS * DDIM];
__device__ float g_rs11p[NROWS * NBLK];
__device__ float g_rs22p[NROWS * NBLK];
__device__ float g_rs12p[NROWS * NBLK];
__device__ float g_cs12p[NROWS * NBLK];
__device__ float g_d12 [NROWS];
__device__ float g_loss[NROWS];

// ====================== helpers ======================
__device__ __forceinline__ uint32_t smem_u32(const void* p) {
    uint32_t a;
    asm("{ .reg .u64 t; cvta.to.shared.u64 t, %1; cvt.u32.u64 %0, t; }"
        : "=r"(a) : "l"(p));
    return a;
}
__device__ __forceinline__ void ldsm_x4(uint32_t (&r)[4], uint32_t addr) {
    asm volatile("ldmatrix.sync.aligned.m8n8.x4.shared.b16 {%0,%1,%2,%3}, [%4];"
        : "=r"(r[0]), "=r"(r[1]), "=r"(r[2]), "=r"(r[3]) : "r"(addr));
}
__device__ __forceinline__ void mma16816(float (&d)[4], const uint32_t (&a)[4],
                                         uint32_t b0, uint32_t b1) {
    asm volatile("mma.sync.aligned.m16n8k16.row.col.f32.bf16.bf16.f32 "
        "{%0,%1,%2,%3}, {%4,%5,%6,%7}, {%8,%9}, {%0,%1,%2,%3};"
        : "+f"(d[0]), "+f"(d[1]), "+f"(d[2]), "+f"(d[3])
        : "r"(a[0]), "r"(a[1]), "r"(a[2]), "r"(a[3]), "r"(b0), "r"(b1));
}
// fp8 e4m3 MMA with f16 accumulators (2 regs = 4 halves)
__device__ __forceinline__ void mma16832_fp8h(uint32_t (&d)[2], const uint32_t (&a)[4],
                                              uint32_t b0, uint32_t b1) {
    asm volatile("mma.sync.aligned.m16n8k32.row.col.f16.e4m3.e4m3.f16 "
        "{%0,%1}, {%2,%3,%4,%5}, {%6,%7}, {%0,%1};"
        : "+r"(d[0]), "+r"(d[1])
        : "r"(a[0]), "r"(a[1]), "r"(a[2]), "r"(a[3]), "r"(b0), "r"(b1));
}
#define CP16(dst, src) \
    asm volatile("cp.async.cg.shared.global [%0], [%1], 16;" :: "r"(dst), "l"(src))
#define CPCOMMIT() asm volatile("cp.async.commit_group;" ::: "memory")
#define CPWAIT(n)  asm volatile("cp.async.wait_group %0;" :: "n"(n) : "memory")

__device__ __forceinline__ float fast_exp2(float x) {
    float y; asm("ex2.approx.f32 %0, %1;" : "=f"(y) : "f"(x)); return y;
}
__device__ __forceinline__ float2 bf2f(uint32_t u) {
    __nv_bfloat162 b = *(__nv_bfloat162*)&u;
    return make_float2(__bfloat162float(b.x), __bfloat162float(b.y));
}

// ============ fused convert: W1|W2|pri|aux -> bf16 in one launch ============
__global__ void __launch_bounds__(256)
convert_kernel(const float* __restrict__ W1, const float* __restrict__ W2,
               const float* __restrict__ pri, const float* __restrict__ aux,
               __nv_bfloat16* __restrict__ Wb, __nv_bfloat16* __restrict__ Zb) {
    const int b = blockIdx.x;
    const float* X;
    __nv_bfloat16* O;
    size_t base;
    if (b < 256)       { X = W1;  O = Wb;                          base = (size_t)b * 1024; }
    else if (b < 512)  { X = W2;  O = Wb + (size_t)DDIM * DDIM;    base = (size_t)(b - 256) * 1024; }
    else if (b < 4608) { X = pri; O = Zb;                          base = (size_t)(b - 512) * 1024; }
    else               { X = aux; O = Zb + ZSTRIDE;                base = (size_t)(b - 4608) * 1024; }
    const size_t i = base + (size_t)threadIdx.x * 4;
    float4 v = *(const float4*)(X + i);
    __nv_bfloat162 p0 = __floats2bfloat162_rn(v.x, v.y);
    __nv_bfloat162 p1 = __floats2bfloat162_rn(v.z, v.w);
    *(uint2*)(O + i) = make_uint2(*(uint32_t*)&p0, *(uint32_t*)&p1);
}

// ==== bf16 proj GEMM core: 128B K-chunks (8 chunks), 3-stage cp.async ======
__device__ __forceinline__ void gemm_tile_bf16w(const char* Ag, const char* Wg,
                                                uint32_t s0,
                                                float (&acc)[2][8][4],
                                                int tid, int lane, int warp_m, int warp_n) {
    const int q = lane >> 3, rr = lane & 7;
    const uint32_t lds_off = (uint32_t)(((q & 1) * 8 + rr) * LDW + (q >> 1) * 16);
    const uint32_t am_off = (uint32_t)(warp_m * 32) * LDW + lds_off;
    const uint32_t bn_off = 128u * LDW + (uint32_t)(warp_n * 64) * LDW + lds_off;

    auto load_chunk = [&](int kc, int stg) {
        const uint32_t b = s0 + stg * GSTG;
#pragma unroll
        for (int it = 0; it < 8; it++) {
            const int u = it * 256 + tid;
            const int m = u >> 10;
            const int row = (u >> 3) & 127;
            const int g = u & 7;
            const char* src = (m ? Wg : Ag) + (size_t)row * (DDIM * 2)
                              + (size_t)kc * 128 + g * 16;
            CP16(b + (uint32_t)m * (128u * LDW) + (uint32_t)row * LDW + g * 16, src);
        }
        CPCOMMIT();
    };

    load_chunk(0, 0);
    load_chunk(1, 1);
    int cur = 0;
    for (int kc = 0; kc < 8; kc++) {
        if (kc < 7) { CPWAIT(1); } else { CPWAIT(0); }
        __syncthreads();
        if (kc + 2 < 8) {
            int iss = cur + 2; if (iss >= 3) iss -= 3;
            load_chunk(kc + 2, iss);
        }
        const uint32_t b = s0 + cur * GSTG;
        const uint32_t a_base = b + am_off;
        const uint32_t b_base = b + bn_off;
#pragma unroll
        for (int kk = 0; kk < 4; kk++) {
            uint32_t af[2][4];
            ldsm_x4(af[0], a_base + kk * 32);
            ldsm_x4(af[1], a_base + 16 * LDW + kk * 32);
#pragma unroll
            for (int n2 = 0; n2 < 4; n2++) {
                uint32_t bf[4];
                ldsm_x4(bf, b_base + n2 * 16 * LDW + kk * 32);
#pragma unroll
                for (int mt = 0; mt < 2; mt++)
#pragma unroll
                    for (int u = 0; u < 2; u++)
                        mma16816(acc[mt][n2 * 2 + u], af[mt], bf[u], bf[u + 2]);
            }
        }
        cur = (cur + 1 == 3) ? 0 : cur + 1;
    }
    __syncthreads();
}

// ============ bf16 projection GEMM (z-batched over embeddings) ==============
template <bool DO_ELU>
__global__ void __launch_bounds__(256, 2)
proj_kernel(const __nv_bfloat16* __restrict__ A, const __nv_bfloat16* __restrict__ W,
            const float* __restrict__ bias, __nv_bfloat16* __restrict__ Ob) {
    extern __shared__ __align__(128) char dynsm[];
    const int tid = threadIdx.x, lane = tid & 31, wid = tid >> 5;
    const int warp_m = wid & 3, warp_n = wid >> 2;
    const int cb = blockIdx.x, rb = blockIdx.y;
    const size_t zoff = (size_t)blockIdx.z * ZSTRIDE;

    float acc[2][8][4] = {};
    gemm_tile_bf16w((const char*)(A + zoff + (size_t)rb * TS * DDIM),
                    (const char*)(W + (size_t)cb * TS * DDIM),
                    smem_u32(dynsm), acc, tid, lane, warp_m, warp_n);

    const int cbase = cb * TS + warp_n * 64;
    const int rbase = rb * TS + warp_m * 32 + (lane >> 2);
#pragma unroll
    for (int mt = 0; mt < 2; mt++) {
        const int ra = rbase + mt * 16, rbb = ra + 8;
#pragma unroll
        for (int nt = 0; nt < 8; nt++) {
            const int c = cbase + nt * 8 + (lane & 3) * 2;
            const float bv0 = bias[c], bv1 = bias[c + 1];
            float x00 = acc[mt][nt][0] + bv0, x01 = acc[mt][nt][1] + bv1;
            float x10 = acc[mt][nt][2] + bv0, x11 = acc[mt][nt][3] + bv1;
            if (DO_ELU) {
                x00 = (x00 > 0.0f) ? x00 : expm1f(x00);
                x01 = (x01 > 0.0f) ? x01 : expm1f(x01);
                x10 = (x10 > 0.0f) ? x10 : expm1f(x10);
                x11 = (x11 > 0.0f) ? x11 : expm1f(x11);
            }
            __nv_bfloat162 p = __floats2bfloat162_rn(x00, x01);
            __nv_bfloat162 q2 = __floats2bfloat162_rn(x10, x11);
            *(uint32_t*)(Ob + zoff + (size_t)ra  * DDIM + c) = *(uint32_t*)&p;
            *(uint32_t*)(Ob + zoff + (size_t)rbb * DDIM + c) = *(uint32_t*)&q2;
        }
    }
}

// ======= similarity tile core (fp8, f16 acc, 128B chunks, 3 stages) ========
__device__ __forceinline__ void sim_tile_mma_fp8(const char* Ag, const char* Bg,
                                                 uint32_t s0,
                                                 uint32_t (&acc)[2][8][2],
                                                 int tid, int lane, int warp_m, int warp_n) {
    const int q = lane >> 3, rr = lane & 7;
    const uint32_t lds_off = (uint32_t)(((q & 1) * 8 + rr) * LDW + (q >> 1) * 16);
    const uint32_t am_off = (uint32_t)(warp_m * 32) * LDW + lds_off;
    const uint32_t bn_off = 128u * LDW + (uint32_t)(warp_n * 64) * LDW + lds_off;

    auto load_chunk = [&](int kc, int stg) {
        const uint32_t b = s0 + stg * GSTG;
#pragma unroll
        for (int it = 0; it < 8; it++) {
            const int u = it * 256 + tid;
            const int m = u >> 10;
            const int row = (u >> 3) & 127;
            const int g = u & 7;
            const char* src = (m ? Bg : Ag) + (size_t)row * DDIM
                              + (size_t)kc * 128 + g * 16;
            CP16(b + (uint32_t)m * (128u * LDW) + (uint32_t)row * LDW + g * 16, src);
        }
        CPCOMMIT();
    };

    load_chunk(0, 0);
    load_chunk(1, 1);
    int cur = 0;
    for (int kc = 0; kc < 4; kc++) {
        if (kc < 3) { CPWAIT(1); } else { CPWAIT(0); }
        __syncthreads();
        if (kc + 2 < 4) {
            int iss = cur + 2; if (iss >= 3) iss -= 3;
            load_chunk(kc + 2, iss);
        }
        const uint32_t b = s0 + cur * GSTG;
        const uint32_t a_base = b + am_off;
        const uint32_t b_base = b + bn_off;
#pragma unroll
        for (int kk = 0; kk < 4; kk++) {
            uint32_t af[2][4];
            ldsm_x4(af[0], a_base + kk * 32);
            ldsm_x4(af[1], a_base + 16 * LDW + kk * 32);
#pragma unroll
            for (int n2 = 0; n2 < 4; n2++) {
                uint32_t bf[4];
                ldsm_x4(bf, b_base + n2 * 16 * LDW + kk * 32);
#pragma unroll
                for (int mt = 0; mt < 2; mt++)
#pragma unroll
                    for (int u = 0; u < 2; u++)
                        mma16832_fp8h(acc[mt][n2 * 2 + u], af[mt], bf[u], bf[u + 2]);
            }
        }
        cur = (cur + 1 == 3) ? 0 : cur + 1;
    }
    __syncthreads();
}

// exp + row/col reductions (acc halves hold dot * 256)
__device__ __forceinline__ void sim_reduce(uint32_t (&acc)[2][8][2], char* sm,
                                           int lane, int warp_m, int warp_n,
                                           bool do_col) {
    float* rs_sm = (float*)sm;
    float* cs_sm = (float*)(sm + 1024);
    const float C = 2.8853900817779268f / (FP8SCALE * FP8SCALE);
    float rs_acc[2][2] = {};
    float cs2[8][2];
    if (do_col)
#pragma unroll
        for (int nt = 0; nt < 8; nt++) cs2[nt][0] = cs2[nt][1] = 0.0f;

#pragma unroll
    for (int mt = 0; mt < 2; mt++)
#pragma unroll
        for (int nt = 0; nt < 8; nt++) {
            float2 f01 = __half22float2(*(__half2*)&acc[mt][nt][0]);  // c0, c1
            float2 f23 = __half22float2(*(__half2*)&acc[mt][nt][1]);  // c2, c3
            float e0 = fast_exp2(f01.x * C);
            float e1 = fast_exp2(f01.y * C);
            float e2 = fast_exp2(f23.x * C);
            float e3 = fast_exp2(f23.y * C);
            rs_acc[mt][0] += e0 + e1;
            rs_acc[mt][1] += e2 + e3;
            if (do_col) { cs2[nt][0] += e0 + e2; cs2[nt][1] += e1 + e3; }
        }

#pragma unroll
    for (int mt = 0; mt < 2; mt++)
#pragma unroll
        for (int half = 0; half < 2; half++) {
            float v = rs_acc[mt][half];
            v += __shfl_xor_sync(0xffffffffu, v, 1);
            v += __shfl_xor_sync(0xffffffffu, v, 2);
            if ((lane & 3) == 0) {
                int row = warp_m * 32 + mt * 16 + half * 8 + (lane >> 2);
                rs_sm[row * 2 + warp_n] = v;
            }
        }
    if (do_col) {
#pragma unroll
        for (int nt = 0; nt < 8; nt++)
#pragma unroll
            for (int e = 0; e < 2; e++) {
                float v = cs2[nt][e];
                v += __shfl_xor_sync(0xffffffffu, v, 4);
                v += __shfl_xor_sync(0xffffffffu, v, 8);
                v += __shfl_xor_sync(0xffffffffu, v, 16);
                if (lane < 4) {
                    int col = warp_n * 64 + nt * 8 + lane * 2 + e;
                    cs_sm[warp_m * 128 + col] = v;
                }
            }
    }
    __syncthreads();
}

// ============ unified similarity kernel: all 8256 tiles in ONE launch =======
__global__ void __launch_bounds__(256, 2)
sim_all_kernel(const uint8_t* __restrict__ F1, const uint8_t* __restrict__ F2,
               float* __restrict__ rs11p, float* __restrict__ rs22p,
               float* __restrict__ rs12p, float* __restrict__ cs12p) {
    extern __shared__ __align__(128) char dynsm[];
    const int bid = blockIdx.x;
    const int tid = threadIdx.x, lane = tid & 31, wid = tid >> 5;
    const int warp_m = wid & 3, warp_n = wid >> 2;

    const uint8_t *A, *B;
    float *rsp, *csp;
    int rb, cb;
    bool diag = false, sym;

    if (bid < 2 * NSYM) {
        sym = true;
        const int z = (bid >= NSYM) ? 1 : 0;
        const int idx = bid - z * NSYM;
        int r = (int)(NBLK + 0.5f - sqrtf((NBLK + 0.5f) * (NBLK + 0.5f) - 2.0f * idx));
        if (r < 0) r = 0;
        if (r > NBLK - 1) r = NBLK - 1;
#define TRI_BASE(x) ((x) * NBLK - ((x) * ((x) - 1)) / 2)
        while (r + 1 <= NBLK - 1 && TRI_BASE(r + 1) <= idx) r++;
        while (r > 0 && TRI_BASE(r) > idx) r--;
        rb = r;
        cb = r + (idx - TRI_BASE(r));
#undef TRI_BASE
        A = z ? F2 : F1;
        B = A;
        rsp = z ? rs22p : rs11p;
        csp = nullptr;
        diag = (rb == cb);
    } else {
        sym = false;
        const int idx = bid - 2 * NSYM;
        rb = idx >> 6;
        cb = idx & (NBLK - 1);
        A = F1; B = F2;
        rsp = rs12p; csp = cs12p;
    }

    uint32_t acc[2][8][2] = {};
    sim_tile_mma_fp8((const char*)(A + (size_t)rb * TS * DDIM),
                     (const char*)(B + (size_t)cb * TS * DDIM),
                     smem_u32(dynsm), acc, tid, lane, warp_m, warp_n);
    sim_reduce(acc, dynsm, lane, warp_m, warp_n, !diag);

    float* rs_sm = (float*)dynsm;
    float* cs_sm = (float*)(dynsm + 1024);
    if (tid < TS) {
        rsp[(size_t)(rb * TS + tid) * NBLK + cb] = rs_sm[tid * 2] + rs_sm[tid * 2 + 1];
        if (!diag) {
            const float ctot = cs_sm[tid] + cs_sm[128 + tid] +
                               cs_sm[256 + tid] + cs_sm[384 + tid];
            if (sym) rsp[(size_t)(cb * TS + tid) * NBLK + rb] = ctot;
            else     csp[(size_t)(cb * TS + tid) * NBLK + rb] = ctot;
        }
    }
}

// ------- fused: L2-normalize both embeddings (bf16 in), d12, fp8 out -------
__global__ void __launch_bounds__(256)
normd12_kernel(const __nv_bfloat16* __restrict__ Hb, uint8_t* __restrict__ F1,
               uint8_t* __restrict__ F2, float* __restrict__ d12) {
    const int row  = blockIdx.x * 8 + (threadIdx.x >> 5);
    const int lane = threadIdx.x & 31;
    const uint4* h1 = (const uint4*)(Hb + (size_t)row * DDIM);
    const uint4* h2 = (const uint4*)(Hb + ZSTRIDE + (size_t)row * DDIM);
    float a1[16], a2[16];
    float ss1 = 0.0f, ss2 = 0.0f, dd = 0.0f;
#pragma unroll
    for (int m = 0; m < 2; m++) {
        uint4 u = h1[lane + 32 * m];
        uint4 w = h2[lane + 32 * m];
        const uint32_t up[4] = {u.x, u.y, u.z, u.w};
        const uint32_t wp[4] = {w.x, w.y, w.z, w.w};
#pragma unroll
        for (int k = 0; k < 4; k++) {
            float2 f1 = bf2f(up[k]);
            float2 f2 = bf2f(wp[k]);
            a1[m * 8 + k * 2]     = f1.x;
            a1[m * 8 + k * 2 + 1] = f1.y;
            a2[m * 8 + k * 2]     = f2.x;
            a2[m * 8 + k * 2 + 1] = f2.y;
            ss1 += f1.x * f1.x + f1.y * f1.y;
            ss2 += f2.x * f2.x + f2.y * f2.y;
            dd  += f1.x * f2.x + f1.y * f2.y;
        }
    }
#pragma unroll
    for (int o = 16; o > 0; o >>= 1) {
        ss1 += __shfl_xor_sync(0xffffffffu, ss1, o);
        ss2 += __shfl_xor_sync(0xffffffffu, ss2, o);
        dd  += __shfl_xor_sync(0xffffffffu, dd,  o);
    }
    const float inv1 = 1.0f / fmaxf(sqrtf(ss1), 1e-12f);
    const float inv2 = 1.0f / fmaxf(sqrtf(ss2), 1e-12f);
    const float s1 = inv1 * FP8SCALE, s2 = inv2 * FP8SCALE;
#pragma unroll
    for (int m = 0; m < 2; m++)
#pragma unroll
        for (int k = 0; k < 2; k++) {
            const int e = m * 8 + k * 4;
            __nv_fp8x2_storage_t lo1 = __nv_cvt_float2_to_fp8x2(
                make_float2(a1[e] * s1, a1[e + 1] * s1), __NV_SATFINITE, __NV_E4M3);
            __nv_fp8x2_storage_t hi1 = __nv_cvt_float2_to_fp8x2(
                make_float2(a1[e + 2] * s1, a1[e + 3] * s1), __NV_SATFINITE, __NV_E4M3);
            *(uint32_t*)(F1 + (size_t)row * DDIM + (lane + 32 * m) * 8 + k * 4) =
                (uint32_t)lo1 | ((uint32_t)hi1 << 16);
            __nv_fp8x2_storage_t lo2 = __nv_cvt_float2_to_fp8x2(
                make_float2(a2[e] * s2, a2[e + 1] * s2), __NV_SATFINITE, __NV_E4M3);
            __nv_fp8x2_storage_t hi2 = __nv_cvt_float2_to_fp8x2(
                make_float2(a2[e + 2] * s2, a2[e + 3] * s2), __NV_SATFINITE, __NV_E4M3);
            *(uint32_t*)(F2 + (size_t)row * DDIM + (lane + 32 * m) * 8 + k * 4) =
                (uint32_t)lo2 | ((uint32_t)hi2 << 16);
        }
    if (lane == 0) d12[row] = dd * inv1 * inv2;
}

__global__ void __launch_bounds__(256)
rowloss_kernel(const float* __restrict__ rs11p, const float* __restrict__ rs22p,
               const float* __restrict__ rs12p, const float* __restrict__ cs12p,
               const float* __restrict__ d12, float* __restrict__ loss) {
    const int row  = blockIdx.x * 8 + (threadIdx.x >> 5);
    const int lane = threadIdx.x & 31;
    float s11 = 0.0f, s22 = 0.0f, s12 = 0.0f, c12 = 0.0f;
    for (int m = lane; m < NBLK; m += 32) {
        const size_t o = (size_t)row * NBLK + m;
        s11 += rs11p[o];
        s22 += rs22p[o];
        s12 += rs12p[o];
        c12 += cs12p[o];
    }
#pragma unroll
    for (int o = 16; o > 0; o >>= 1) {
        s11 += __shfl_xor_sync(0xffffffffu, s11, o);
        s22 += __shfl_xor_sync(0xffffffffu, s22, o);
        s12 += __shfl_xor_sync(0xffffffffu, s12, o);
        c12 += __shfl_xor_sync(0xffffffffu, c12, o);
    }
    if (lane == 0) {
        const float E2 = 7.38905609893065f;   // exp(1/tau)
        const float den1 = s11 + s12 - E2;
        const float den2 = s22 + c12 - E2;
        loss[row] = -2.0f * d12[row] + 0.5f * (__logf(den1) + __logf(den2));
    }
}

__global__ void __launch_bounds__(1024)
final_kernel(const float* __restrict__ loss, float* __restrict__ out) {
    __shared__ float sm[1024];
    const int t = threadIdx.x;
    float s = 0.0f;
    for (int i = t; i < NROWS; i += 1024) s += loss[i];
    sm[t] = s;
    __syncthreads();
    for (int o = 512; o > 0; o >>= 1) {
        if (t < o) sm[t] += sm[t + o];
        __syncthreads();
    }
    if (t == 0) out[0] = sm[0] * (1.0f / NROWS);
}

// ---------------- launch ----------------------------------------------------
extern "C" void kernel_launch(void* const* d_in, const int* in_sizes, int n_in,
                              void* d_out, int out_size) {
    const float* pri = (const float*)d_in[0];
    const float* aux = (const float*)d_in[1];
    const float* W1  = (const float*)d_in[2];
    const float* b1  = (const float*)d_in[3];
    const float* W2  = (const float*)d_in[4];
    const float* b2  = (const float*)d_in[5];
    float* out = (float*)d_out;

    __nv_bfloat16 *Zb, *Tb, *Wb, *Hb;
    uint8_t *F1, *F2;
    float *rs11p, *rs22p, *rs12p, *cs12p, *d12, *loss;
    cudaGetSymbolAddress((void**)&Zb,  g_Zb);
    cudaGetSymbolAddress((void**)&Tb,  g_Tb);
    cudaGetSymbolAddress((void**)&Wb,  g_Wb);
    cudaGetSymbolAddress((void**)&Hb,  g_Hb);
    cudaGetSymbolAddress((void**)&F1,  g_F1);
    cudaGetSymbolAddress((void**)&F2,  g_F2);
    cudaGetSymbolAddress((void**)&rs11p, g_rs11p);
    cudaGetSymbolAddress((void**)&rs22p, g_rs22p);
    cudaGetSymbolAddress((void**)&rs12p, g_rs12p);
    cudaGetSymbolAddress((void**)&cs12p, g_cs12p);
    cudaGetSymbolAddress((void**)&d12,  g_d12);
    cudaGetSymbolAddress((void**)&loss, g_loss);

    const int gemmSmem = 3 * GSTG;   // 110592
    cudaFuncSetAttribute(proj_kernel<true >,
                         cudaFuncAttributeMaxDynamicSharedMemorySize, gemmSmem);
    cudaFuncSetAttribute(proj_kernel<false>,
                         cudaFuncAttributeMaxDynamicSharedMemorySize, gemmSmem);
    cudaFuncSetAttribute(sim_all_kernel,
                         cudaFuncAttributeMaxDynamicSharedMemorySize, gemmSmem);

    const dim3 pg(DDIM / TS, NROWS / TS, 2);        // (4, 64, 2)
    const int simBlocks = 2 * NSYM + NBLK * NBLK;   // 8256
    const int cvtBlocks = 512 + 2 * (NROWS * DDIM / 1024);   // 8704

    convert_kernel<<<cvtBlocks, 256>>>(W1, W2, pri, aux, Wb, Zb);

    proj_kernel<true ><<<pg, 256, gemmSmem>>>(Zb, Wb, b1, Tb);
    proj_kernel<false><<<pg, 256, gemmSmem>>>(Tb, Wb + (size_t)DDIM * DDIM, b2, Hb);

    normd12_kernel<<<NROWS / 8, 256>>>(Hb, F1, F2, d12);

    sim_all_kernel<<<simBlocks, 256, gemmSmem>>>(F1, F2, rs11p, rs22p, rs12p, cs12p);

    rowloss_kernel<<<NROWS / 8, 256>>>(rs11p, rs22p, rs12p, cs12p, d12, loss);
    final_kernel<<<1, 1024>>>(loss, out);
}

// round 16
// speedup vs baseline: 1.0881x; 1.0023x over previous
#include <cuda_runtime.h>
#include <cuda_bf16.h>
#include <cuda_fp16.h>
#include <cuda_fp8.h>
#include <math.h>
#include <stdint.h>

#define NROWS 8192
#define DDIM  512
#define TS    128
#define NBLK  (NROWS / TS)        // 64
#define LDW   144                 // smem row stride: 128B data + 16B pad
#define GSTG  (2 * 128 * LDW)     // 36864 per stage
#define NSYM  (NBLK * (NBLK + 1) / 2)   // 2080
#define ZSTRIDE ((size_t)NROWS * DDIM)
#define FP8SCALE 16.0f

// ---------------- device scratch ----------------
__device__ __half g_Zh[2 * NROWS * DDIM];
__device__ __half g_Th[2 * NROWS * DDIM];
__device__ __half g_Wh[2 * DDIM * DDIM];
__device__ __half g_Hh[2 * NROWS * DDIM];   // layer-2 out, f16
__device__ uint8_t g_F1[NROWS * DDIM];   // fp8 e4m3, scaled by 16
__device__ uint8_t g_F2[NROWS * DDIM];
__device__ float g_rs11p[NROWS * NBLK];
__device__ float g_rs22p[NROWS * NBLK];
__device__ float g_rs12p[NROWS * NBLK];
__device__ float g_cs12p[NROWS * NBLK];
__device__ float g_d12 [NROWS];
__device__ float g_loss[NROWS];

// ====================== helpers ======================
__device__ __forceinline__ uint32_t smem_u32(const void* p) {
    uint32_t a;
    asm("{ .reg .u64 t; cvta.to.shared.u64 t, %1; cvt.u32.u64 %0, t; }"
        : "=r"(a) : "l"(p));
    return a;
}
__device__ __forceinline__ void ldsm_x4(uint32_t (&r)[4], uint32_t addr) {
    asm volatile("ldmatrix.sync.aligned.m8n8.x4.shared.b16 {%0,%1,%2,%3}, [%4];"
        : "=r"(r[0]), "=r"(r[1]), "=r"(r[2]), "=r"(r[3]) : "r"(addr));
}
// f16 MMA with f16 accumulators (2 regs = 4 halves)
__device__ __forceinline__ void mma16816h(uint32_t (&d)[2], const uint32_t (&a)[4],
                                          uint32_t b0, uint32_t b1) {
    asm volatile("mma.sync.aligned.m16n8k16.row.col.f16.f16.f16.f16 "
        "{%0,%1}, {%2,%3,%4,%5}, {%6,%7}, {%0,%1};"
        : "+r"(d[0]), "+r"(d[1])
        : "r"(a[0]), "r"(a[1]), "r"(a[2]), "r"(a[3]), "r"(b0), "r"(b1));
}
// fp8 e4m3 MMA with f16 accumulators (2 regs = 4 halves)
__device__ __forceinline__ void mma16832_fp8h(uint32_t (&d)[2], const uint32_t (&a)[4],
                                              uint32_t b0, uint32_t b1) {
    asm volatile("mma.sync.aligned.m16n8k32.row.col.f16.e4m3.e4m3.f16 "
        "{%0,%1}, {%2,%3,%4,%5}, {%6,%7}, {%0,%1};"
        : "+r"(d[0]), "+r"(d[1])
        : "r"(a[0]), "r"(a[1]), "r"(a[2]), "r"(a[3]), "r"(b0), "r"(b1));
}
#define CP16(dst, src) \
    asm volatile("cp.async.cg.shared.global [%0], [%1], 16;" :: "r"(dst), "l"(src))
#define CPCOMMIT() asm volatile("cp.async.commit_group;" ::: "memory")
#define CPWAIT(n)  asm volatile("cp.async.wait_group %0;" :: "n"(n) : "memory")

__device__ __forceinline__ float fast_exp2(float x) {
    float y; asm("ex2.approx.f32 %0, %1;" : "=f"(y) : "f"(x)); return y;
}

// ============ fused convert: W1|W2|pri|aux -> f16 in one launch =============
__global__ void __launch_bounds__(256)
convert_kernel(const float* __restrict__ W1, const float* __restrict__ W2,
               const float* __restrict__ pri, const float* __restrict__ aux,
               __half* __restrict__ Wh, __half* __restrict__ Zh) {
    const int b = blockIdx.x;
    const float* X;
    __half* O;
    size_t base;
    if (b < 256)       { X = W1;  O = Wh;                          base = (size_t)b * 1024; }
    else if (b < 512)  { X = W2;  O = Wh + (size_t)DDIM * DDIM;    base = (size_t)(b - 256) * 1024; }
    else if (b < 4608) { X = pri; O = Zh;                          base = (size_t)(b - 512) * 1024; }
    else               { X = aux; O = Zh + ZSTRIDE;                base = (size_t)(b - 4608) * 1024; }
    const size_t i = base + (size_t)threadIdx.x * 4;
    float4 v = *(const float4*)(X + i);
    __half2 p0 = __floats2half2_rn(v.x, v.y);
    __half2 p1 = __floats2half2_rn(v.z, v.w);
    *(uint2*)(O + i) = make_uint2(*(uint32_t*)&p0, *(uint32_t*)&p1);
}

// ==== f16 proj GEMM core: 128B K-chunks (8 chunks), 3-stage cp.async =======
__device__ __forceinline__ void gemm_tile_f16(const char* Ag, const char* Wg,
                                              uint32_t s0,
                                              uint32_t (&acc)[2][8][2],
                                              int tid, int lane, int warp_m, int warp_n) {
    const int q = lane >> 3, rr = lane & 7;
    const uint32_t lds_off = (uint32_t)(((q & 1) * 8 + rr) * LDW + (q >> 1) * 16);
    const uint32_t am_off = (uint32_t)(warp_m * 32) * LDW + lds_off;
    const uint32_t bn_off = 128u * LDW + (uint32_t)(warp_n * 64) * LDW + lds_off;

    auto load_chunk = [&](int kc, int stg) {
        const uint32_t b = s0 + stg * GSTG;
#pragma unroll
        for (int it = 0; it < 8; it++) {
            const int u = it * 256 + tid;
            const int m = u >> 10;
            const int row = (u >> 3) & 127;
            const int g = u & 7;
            const char* src = (m ? Wg : Ag) + (size_t)row * (DDIM * 2)
                              + (size_t)kc * 128 + g * 16;
            CP16(b + (uint32_t)m * (128u * LDW) + (uint32_t)row * LDW + g * 16, src);
        }
        CPCOMMIT();
    };

    load_chunk(0, 0);
    load_chunk(1, 1);
    int cur = 0;
    for (int kc = 0; kc < 8; kc++) {
        if (kc < 7) { CPWAIT(1); } else { CPWAIT(0); }
        __syncthreads();
        if (kc + 2 < 8) {
            int iss = cur + 2; if (iss >= 3) iss -= 3;
            load_chunk(kc + 2, iss);
        }
        const uint32_t b = s0 + cur * GSTG;
        const uint32_t a_base = b + am_off;
        const uint32_t b_base = b + bn_off;
#pragma unroll
        for (int kk = 0; kk < 4; kk++) {
            uint32_t af[2][4];
            ldsm_x4(af[0], a_base + kk * 32);
            ldsm_x4(af[1], a_base + 16 * LDW + kk * 32);
#pragma unroll
            for (int n2 = 0; n2 < 4; n2++) {
                uint32_t bf[4];
                ldsm_x4(bf, b_base + n2 * 16 * LDW + kk * 32);
#pragma unroll
                for (int mt = 0; mt < 2; mt++)
#pragma unroll
                    for (int u = 0; u < 2; u++)
                        mma16816h(acc[mt][n2 * 2 + u], af[mt], bf[u], bf[u + 2]);
            }
        }
        cur = (cur + 1 == 3) ? 0 : cur + 1;
    }
    __syncthreads();
}

// ============ f16 projection GEMM (z-batched over embeddings) ===============
template <bool DO_ELU>
__global__ void __launch_bounds__(256, 2)
proj_kernel(const __half* __restrict__ A, const __half* __restrict__ W,
            const float* __restrict__ bias, __half* __restrict__ Oh) {
    extern __shared__ __align__(128) char dynsm[];
    const int tid = threadIdx.x, lane = tid & 31, wid = tid >> 5;
    const int warp_m = wid & 3, warp_n = wid >> 2;
    const int cb = blockIdx.x, rb = blockIdx.y;
    const size_t zoff = (size_t)blockIdx.z * ZSTRIDE;

    uint32_t acc[2][8][2] = {};
    gemm_tile_f16((const char*)(A + zoff + (size_t)rb * TS * DDIM),
                  (const char*)(W + (size_t)cb * TS * DDIM),
                  smem_u32(dynsm), acc, tid, lane, warp_m, warp_n);

    const int cbase = cb * TS + warp_n * 64;
    const int rbase = rb * TS + warp_m * 32 + (lane >> 2);
#pragma unroll
    for (int mt = 0; mt < 2; mt++) {
        const int ra = rbase + mt * 16, rbb = ra + 8;
#pragma unroll
        for (int nt = 0; nt < 8; nt++) {
            const int c = cbase + nt * 8 + (lane & 3) * 2;
            const float bv0 = bias[c], bv1 = bias[c + 1];
            float2 f01 = __half22float2(*(__half2*)&acc[mt][nt][0]);  // row ra
            float2 f23 = __half22float2(*(__half2*)&acc[mt][nt][1]);  // row rbb
            float x00 = f01.x + bv0, x01 = f01.y + bv1;
            float x10 = f23.x + bv0, x11 = f23.y + bv1;
            if (DO_ELU) {
                x00 = (x00 > 0.0f) ? x00 : expm1f(x00);
                x01 = (x01 > 0.0f) ? x01 : expm1f(x01);
                x10 = (x10 > 0.0f) ? x10 : expm1f(x10);
                x11 = (x11 > 0.0f) ? x11 : expm1f(x11);
            }
            __half2 p = __floats2half2_rn(x00, x01);
            __half2 q2 = __floats2half2_rn(x10, x11);
            *(uint32_t*)(Oh + zoff + (size_t)ra  * DDIM + c) = *(uint32_t*)&p;
            *(uint32_t*)(Oh + zoff + (size_t)rbb * DDIM + c) = *(uint32_t*)&q2;
        }
    }
}

// ======= similarity tile core (fp8, f16 acc, 128B chunks, 3 stages) ========
__device__ __forceinline__ void sim_tile_mma_fp8(const char* Ag, const char* Bg,
                                                 uint32_t s0,
                                                 uint32_t (&acc)[2][8][2],
                                                 int tid, int lane, int warp_m, int warp_n) {
    const int q = lane >> 3, rr = lane & 7;
    const uint32_t lds_off = (uint32_t)(((q & 1) * 8 + rr) * LDW + (q >> 1) * 16);
    const uint32_t am_off = (uint32_t)(warp_m * 32) * LDW + lds_off;
    const uint32_t bn_off = 128u * LDW + (uint32_t)(warp_n * 64) * LDW + lds_off;

    auto load_chunk = [&](int kc, int stg) {
        const uint32_t b = s0 + stg * GSTG;
#pragma unroll
        for (int it = 0; it < 8; it++) {
            const int u = it * 256 + tid;
            const int m = u >> 10;
            const int row = (u >> 3) & 127;
            const int g = u & 7;
            const char* src = (m ? Bg : Ag) + (size_t)row * DDIM
                              + (size_t)kc * 128 + g * 16;
            CP16(b + (uint32_t)m * (128u * LDW) + (uint32_t)row * LDW + g * 16, src);
        }
        CPCOMMIT();
    };

    load_chunk(0, 0);
    load_chunk(1, 1);
    int cur = 0;
    for (int kc = 0; kc < 4; kc++) {
        if (kc < 3) { CPWAIT(1); } else { CPWAIT(0); }
        __syncthreads();
        if (kc + 2 < 4) {
            int iss = cur + 2; if (iss >= 3) iss -= 3;
            load_chunk(kc + 2, iss);
        }
        const uint32_t b = s0 + cur * GSTG;
        const uint32_t a_base = b + am_off;
        const uint32_t b_base = b + bn_off;
#pragma unroll
        for (int kk = 0; kk < 4; kk++) {
            uint32_t af[2][4];
            ldsm_x4(af[0], a_base + kk * 32);
            ldsm_x4(af[1], a_base + 16 * LDW + kk * 32);
#pragma unroll
            for (int n2 = 0; n2 < 4; n2++) {
                uint32_t bf[4];
                ldsm_x4(bf, b_base + n2 * 16 * LDW + kk * 32);
#pragma unroll
                for (int mt = 0; mt < 2; mt++)
#pragma unroll
                    for (int u = 0; u < 2; u++)
                        mma16832_fp8h(acc[mt][n2 * 2 + u], af[mt], bf[u], bf[u + 2]);
            }
        }
        cur = (cur + 1 == 3) ? 0 : cur + 1;
    }
    __syncthreads();
}

// exp + row/col reductions (acc halves hold dot * 256)
__device__ __forceinline__ void sim_reduce(uint32_t (&acc)[2][8][2], char* sm,
                                           int lane, int warp_m, int warp_n,
                                           bool do_col) {
    float* rs_sm = (float*)sm;
    float* cs_sm = (float*)(sm + 1024);
    const float C = 2.8853900817779268f / (FP8SCALE * FP8SCALE);
    float rs_acc[2][2] = {};
    float cs2[8][2];
    if (do_col)
#pragma unroll
        for (int nt = 0; nt < 8; nt++) cs2[nt][0] = cs2[nt][1] = 0.0f;

#pragma unroll
    for (int mt = 0; mt < 2; mt++)
#pragma unroll
        for (int nt = 0; nt < 8; nt++) {
            float2 f01 = __half22float2(*(__half2*)&acc[mt][nt][0]);
            float2 f23 = __half22float2(*(__half2*)&acc[mt][nt][1]);
            float e0 = fast_exp2(f01.x * C);
            float e1 = fast_exp2(f01.y * C);
            float e2 = fast_exp2(f23.x * C);
            float e3 = fast_exp2(f23.y * C);
            rs_acc[mt][0] += e0 + e1;
            rs_acc[mt][1] += e2 + e3;
            if (do_col) { cs2[nt][0] += e0 + e2; cs2[nt][1] += e1 + e3; }
        }

#pragma unroll
    for (int mt = 0; mt < 2; mt++)
#pragma unroll
        for (int half = 0; half < 2; half++) {
            float v = rs_acc[mt][half];
            v += __shfl_xor_sync(0xffffffffu, v, 1);
            v += __shfl_xor_sync(0xffffffffu, v, 2);
            if ((lane & 3) == 0) {
                int row = warp_m * 32 + mt * 16 + half * 8 + (lane >> 2);
                rs_sm[row * 2 + warp_n] = v;
            }
        }
    if (do_col) {
#pragma unroll
        for (int nt = 0; nt < 8; nt++)
#pragma unroll
            for (int e = 0; e < 2; e++) {
                float v = cs2[nt][e];
                v += __shfl_xor_sync(0xffffffffu, v, 4);
                v += __shfl_xor_sync(0xffffffffu, v, 8);
                v += __shfl_xor_sync(0xffffffffu, v, 16);
                if (lane < 4) {
                    int col = warp_n * 64 + nt * 8 + lane * 2 + e;
                    cs_sm[warp_m * 128 + col] = v;
                }
            }
    }
    __syncthreads();
}

// ============ unified similarity kernel: all 8256 tiles in ONE launch =======
__global__ void __launch_bounds__(256, 2)
sim_all_kernel(const uint8_t* __restrict__ F1, const uint8_t* __restrict__ F2,
               float* __restrict__ rs11p, float* __restrict__ rs22p,
               float* __restrict__ rs12p, float* __restrict__ cs12p) {
    extern __shared__ __align__(128) char dynsm[];
    const int bid = blockIdx.x;
    const int tid = threadIdx.x, lane = tid & 31, wid = tid >> 5;
    const int warp_m = wid & 3, warp_n = wid >> 2;

    const uint8_t *A, *B;
    float *rsp, *csp;
    int rb, cb;
    bool diag = false, sym;

    if (bid < 2 * NSYM) {
        sym = true;
        const int z = (bid >= NSYM) ? 1 : 0;
        const int idx = bid - z * NSYM;
        int r = (int)(NBLK + 0.5f - sqrtf((NBLK + 0.5f) * (NBLK + 0.5f) - 2.0f * idx));
        if (r < 0) r = 0;
        if (r > NBLK - 1) r = NBLK - 1;
#define TRI_BASE(x) ((x) * NBLK - ((x) * ((x) - 1)) / 2)
        while (r + 1 <= NBLK - 1 && TRI_BASE(r + 1) <= idx) r++;
        while (r > 0 && TRI_BASE(r) > idx) r--;
        rb = r;
        cb = r + (idx - TRI_BASE(r));
#undef TRI_BASE
        A = z ? F2 : F1;
        B = A;
        rsp = z ? rs22p : rs11p;
        csp = nullptr;
        diag = (rb == cb);
    } else {
        sym = false;
        const int idx = bid - 2 * NSYM;
        rb = idx >> 6;
        cb = idx & (NBLK - 1);
        A = F1; B = F2;
        rsp = rs12p; csp = cs12p;
    }

    uint32_t acc[2][8][2] = {};
    sim_tile_mma_fp8((const char*)(A + (size_t)rb * TS * DDIM),
                     (const char*)(B + (size_t)cb * TS * DDIM),
                     smem_u32(dynsm), acc, tid, lane, warp_m, warp_n);
    sim_reduce(acc, dynsm, lane, warp_m, warp_n, !diag);

    float* rs_sm = (float*)dynsm;
    float* cs_sm = (float*)(dynsm + 1024);
    if (tid < TS) {
        rsp[(size_t)(rb * TS + tid) * NBLK + cb] = rs_sm[tid * 2] + rs_sm[tid * 2 + 1];
        if (!diag) {
            const float ctot = cs_sm[tid] + cs_sm[128 + tid] +
                               cs_sm[256 + tid] + cs_sm[384 + tid];
            if (sym) rsp[(size_t)(cb * TS + tid) * NBLK + rb] = ctot;
            else     csp[(size_t)(cb * TS + tid) * NBLK + rb] = ctot;
        }
    }
}

// ------- fused: L2-normalize both embeddings (f16 in), d12, fp8 out --------
__global__ void __launch_bounds__(256)
normd12_kernel(const __half* __restrict__ Hh, uint8_t* __restrict__ F1,
               uint8_t* __restrict__ F2, float* __restrict__ d12) {
    const int row  = blockIdx.x * 8 + (threadIdx.x >> 5);
    const int lane = threadIdx.x & 31;
    const uint4* h1 = (const uint4*)(Hh + (size_t)row * DDIM);
    const uint4* h2 = (const uint4*)(Hh + ZSTRIDE + (size_t)row * DDIM);
    float a1[16], a2[16];
    float ss1 = 0.0f, ss2 = 0.0f, dd = 0.0f;
#pragma unroll
    for (int m = 0; m < 2; m++) {
        uint4 u = h1[lane + 32 * m];
        uint4 w = h2[lane + 32 * m];
        const uint32_t up[4] = {u.x, u.y, u.z, u.w};
        const uint32_t wp[4] = {w.x, w.y, w.z, w.w};
#pragma unroll
        for (int k = 0; k < 4; k++) {
            float2 f1 = __half22float2(*(__half2*)&up[k]);
            float2 f2 = __half22float2(*(__half2*)&wp[k]);
            a1[m * 8 + k * 2]     = f1.x;
            a1[m * 8 + k * 2 + 1] = f1.y;
            a2[m * 8 + k * 2]     = f2.x;
            a2[m * 8 + k * 2 + 1] = f2.y;
            ss1 += f1.x * f1.x + f1.y * f1.y;
            ss2 += f2.x * f2.x + f2.y * f2.y;
            dd  += f1.x * f2.x + f1.y * f2.y;
        }
    }
#pragma unroll
    for (int o = 16; o > 0; o >>= 1) {
        ss1 += __shfl_xor_sync(0xffffffffu, ss1, o);
        ss2 += __shfl_xor_sync(0xffffffffu, ss2, o);
        dd  += __shfl_xor_sync(0xffffffffu, dd,  o);
    }
    const float inv1 = 1.0f / fmaxf(sqrtf(ss1), 1e-12f);
    const float inv2 = 1.0f / fmaxf(sqrtf(ss2), 1e-12f);
    const float s1 = inv1 * FP8SCALE, s2 = inv2 * FP8SCALE;
#pragma unroll
    for (int m = 0; m < 2; m++)
#pragma unroll
        for (int k = 0; k < 2; k++) {
            const int e = m * 8 + k * 4;
            __nv_fp8x2_storage_t lo1 = __nv_cvt_float2_to_fp8x2(
                make_float2(a1[e] * s1, a1[e + 1] * s1), __NV_SATFINITE, __NV_E4M3);
            __nv_fp8x2_storage_t hi1 = __nv_cvt_float2_to_fp8x2(
                make_float2(a1[e + 2] * s1, a1[e + 3] * s1), __NV_SATFINITE, __NV_E4M3);
            *(uint32_t*)(F1 + (size_t)row * DDIM + (lane + 32 * m) * 8 + k * 4) =
                (uint32_t)lo1 | ((uint32_t)hi1 << 16);
            __nv_fp8x2_storage_t lo2 = __nv_cvt_float2_to_fp8x2(
                make_float2(a2[e] * s2, a2[e + 1] * s2), __NV_SATFINITE, __NV_E4M3);
            __nv_fp8x2_storage_t hi2 = __nv_cvt_float2_to_fp8x2(
                make_float2(a2[e + 2] * s2, a2[e + 3] * s2), __NV_SATFINITE, __NV_E4M3);
            *(uint32_t*)(F2 + (size_t)row * DDIM + (lane + 32 * m) * 8 + k * 4) =
                (uint32_t)lo2 | ((uint32_t)hi2 << 16);
        }
    if (lane == 0) d12[row] = dd * inv1 * inv2;
}

__global__ void __launch_bounds__(256)
rowloss_kernel(const float* __restrict__ rs11p, const float* __restrict__ rs22p,
               const float* __restrict__ rs12p, const float* __restrict__ cs12p,
               const float* __restrict__ d12, float* __restrict__ loss) {
    const int row  = blockIdx.x * 8 + (threadIdx.x >> 5);
    const int lane = threadIdx.x & 31;
    float s11 = 0.0f, s22 = 0.0f, s12 = 0.0f, c12 = 0.0f;
    for (int m = lane; m < NBLK; m += 32) {
        const size_t o = (size_t)row * NBLK + m;
        s11 += rs11p[o];
        s22 += rs22p[o];
        s12 += rs12p[o];
        c12 += cs12p[o];
    }
#pragma unroll
    for (int o = 16; o > 0; o >>= 1) {
        s11 += __shfl_xor_sync(0xffffffffu, s11, o);
        s22 += __shfl_xor_sync(0xffffffffu, s22, o);
        s12 += __shfl_xor_sync(0xffffffffu, s12, o);
        c12 += __shfl_xor_sync(0xffffffffu, c12, o);
    }
    if (lane == 0) {
        const float E2 = 7.38905609893065f;   // exp(1/tau)
        const float den1 = s11 + s12 - E2;
        const float den2 = s22 + c12 - E2;
        loss[row] = -2.0f * d12[row] + 0.5f * (__logf(den1) + __logf(den2));
    }
}

__global__ void __launch_bounds__(1024)
final_kernel(const float* __restrict__ loss, float* __restrict__ out) {
    __shared__ float sm[1024];
    const int t = threadIdx.x;
    float s = 0.0f;
    for (int i = t; i < NROWS; i += 1024) s += loss[i];
    sm[t] = s;
    __syncthreads();
    for (int o = 512; o > 0; o >>= 1) {
        if (t < o) sm[t] += sm[t + o];
        __syncthreads();
    }
    if (t == 0) out[0] = sm[0] * (1.0f / NROWS);
}

// ---------------- launch ----------------------------------------------------
extern "C" void kernel_launch(void* const* d_in, const int* in_sizes, int n_in,
                              void* d_out, int out_size) {
    const float* pri = (const float*)d_in[0];
    const float* aux = (const float*)d_in[1];
    const float* W1  = (const float*)d_in[2];
    const float* b1  = (const float*)d_in[3];
    const float* W2  = (const float*)d_in[4];
    const float* b2  = (const float*)d_in[5];
    float* out = (float*)d_out;

    __half *Zh, *Th, *Wh, *Hh;
    uint8_t *F1, *F2;
    float *rs11p, *rs22p, *rs12p, *cs12p, *d12, *loss;
    cudaGetSymbolAddress((void**)&Zh,  g_Zh);
    cudaGetSymbolAddress((void**)&Th,  g_Th);
    cudaGetSymbolAddress((void**)&Wh,  g_Wh);
    cudaGetSymbolAddress((void**)&Hh,  g_Hh);
    cudaGetSymbolAddress((void**)&F1,  g_F1);
    cudaGetSymbolAddress((void**)&F2,  g_F2);
    cudaGetSymbolAddress((void**)&rs11p, g_rs11p);
    cudaGetSymbolAddress((void**)&rs22p, g_rs22p);
    cudaGetSymbolAddress((void**)&rs12p, g_rs12p);
    cudaGetSymbolAddress((void**)&cs12p, g_cs12p);
    cudaGetSymbolAddress((void**)&d12,  g_d12);
    cudaGetSymbolAddress((void**)&loss, g_loss);

    const int gemmSmem = 3 * GSTG;   // 110592
    cudaFuncSetAttribute(proj_kernel<true >,
                         cudaFuncAttributeMaxDynamicSharedMemorySize, gemmSmem);
    cudaFuncSetAttribute(proj_kernel<false>,
                         cudaFuncAttributeMaxDynamicSharedMemorySize, gemmSmem);
    cudaFuncSetAttribute(sim_all_kernel,
                         cudaFuncAttributeMaxDynamicSharedMemorySize, gemmSmem);

    const dim3 pg(DDIM / TS, NROWS / TS, 2);        // (4, 64, 2)
    const int simBlocks = 2 * NSYM + NBLK * NBLK;   // 8256
    const int cvtBlocks = 512 + 2 * (NROWS * DDIM / 1024);   // 8704

    convert_kernel<<<cvtBlocks, 256>>>(W1, W2, pri, aux, Wh, Zh);

    proj_kernel<true ><<<pg, 256, gemmSmem>>>(Zh, Wh, b1, Th);
    proj_kernel<false><<<pg, 256, gemmSmem>>>(Th, Wh + (size_t)DDIM * DDIM, b2, Hh);

    normd12_kernel<<<NROWS / 8, 256>>>(Hh, F1, F2, d12);

    sim_all_kernel<<<simBlocks, 256, gemmSmem>>>(F1, F2, rs11p, rs22p, rs12p, cs12p);

    rowloss_kernel<<<NROWS / 8, 256>>>(rs11p, rs22p, rs12p, cs12p, d12, loss);
    final_kernel<<<1, 1024>>>(loss, out);
}

// round 17
// speedup vs baseline: 1.0993x; 1.0103x over previous
#include <cuda_runtime.h>
#include <cuda_bf16.h>
#include <cuda_fp16.h>
#include <cuda_fp8.h>
#include <math.h>
#include <stdint.h>

#define NROWS 8192
#define DDIM  512
#define TS    128
#define NBLK  (NROWS / TS)        // 64
#define LDW   144                 // smem row stride: 128B data + 16B pad
#define GSTG  (2 * 128 * LDW)     // 36864 per stage
#define NSYM  (NBLK * (NBLK + 1) / 2)   // 2080
#define ZSTRIDE ((size_t)NROWS * DDIM)
#define FP8SCALE 16.0f

// ---------------- device scratch ----------------
__device__ __half g_Zh[2 * NROWS * DDIM];
__device__ __half g_Th[2 * NROWS * DDIM];
__device__ __half g_Wh[2 * DDIM * DDIM];
__device__ __half g_Hh[2 * NROWS * DDIM];   // layer-2 out, f16
__device__ uint8_t g_F1[NROWS * DDIM];   // fp8 e4m3, scaled by 16
__device__ uint8_t g_F2[NROWS * DDIM];
__device__ float g_rs11p[NROWS * NBLK];
__device__ float g_rs22p[NROWS * NBLK];
__device__ float g_rs12p[NROWS * NBLK];
__device__ float g_cs12p[NROWS * NBLK];
__device__ float g_d12 [NROWS];
__device__ float g_loss[NROWS];

// ====================== helpers ======================
__device__ __forceinline__ uint32_t smem_u32(const void* p) {
    uint32_t a;
    asm("{ .reg .u64 t; cvta.to.shared.u64 t, %1; cvt.u32.u64 %0, t; }"
        : "=r"(a) : "l"(p));
    return a;
}
__device__ __forceinline__ void ldsm_x4(uint32_t (&r)[4], uint32_t addr) {
    asm volatile("ldmatrix.sync.aligned.m8n8.x4.shared.b16 {%0,%1,%2,%3}, [%4];"
        : "=r"(r[0]), "=r"(r[1]), "=r"(r[2]), "=r"(r[3]) : "r"(addr));
}
// f16 MMA with f16 accumulators (2 regs = 4 halves)
__device__ __forceinline__ void mma16816h(uint32_t (&d)[2], const uint32_t (&a)[4],
                                          uint32_t b0, uint32_t b1) {
    asm volatile("mma.sync.aligned.m16n8k16.row.col.f16.f16.f16.f16 "
        "{%0,%1}, {%2,%3,%4,%5}, {%6,%7}, {%0,%1};"
        : "+r"(d[0]), "+r"(d[1])
        : "r"(a[0]), "r"(a[1]), "r"(a[2]), "r"(a[3]), "r"(b0), "r"(b1));
}
// fp8 e4m3 MMA with f16 accumulators (2 regs = 4 halves)
__device__ __forceinline__ void mma16832_fp8h(uint32_t (&d)[2], const uint32_t (&a)[4],
                                              uint32_t b0, uint32_t b1) {
    asm volatile("mma.sync.aligned.m16n8k32.row.col.f16.e4m3.e4m3.f16 "
        "{%0,%1}, {%2,%3,%4,%5}, {%6,%7}, {%0,%1};"
        : "+r"(d[0]), "+r"(d[1])
        : "r"(a[0]), "r"(a[1]), "r"(a[2]), "r"(a[3]), "r"(b0), "r"(b1));
}
#define CP16(dst, src) \
    asm volatile("cp.async.cg.shared.global [%0], [%1], 16;" :: "r"(dst), "l"(src))
#define CPCOMMIT() asm volatile("cp.async.commit_group;" ::: "memory")
#define CPWAIT(n)  asm volatile("cp.async.wait_group %0;" :: "n"(n) : "memory")

__device__ __forceinline__ float fast_exp2(float x) {
    float y; asm("ex2.approx.f32 %0, %1;" : "=f"(y) : "f"(x)); return y;
}

// ============ fused convert: W1|W2|pri|aux -> f16 in one launch =============
__global__ void __launch_bounds__(256)
convert_kernel(const float* __restrict__ W1, const float* __restrict__ W2,
               const float* __restrict__ pri, const float* __restrict__ aux,
               __half* __restrict__ Wh, __half* __restrict__ Zh) {
    const int b = blockIdx.x;
    const float* X;
    __half* O;
    size_t base;
    if (b < 256)       { X = W1;  O = Wh;                          base = (size_t)b * 1024; }
    else if (b < 512)  { X = W2;  O = Wh + (size_t)DDIM * DDIM;    base = (size_t)(b - 256) * 1024; }
    else if (b < 4608) { X = pri; O = Zh;                          base = (size_t)(b - 512) * 1024; }
    else               { X = aux; O = Zh + ZSTRIDE;                base = (size_t)(b - 4608) * 1024; }
    const size_t i = base + (size_t)threadIdx.x * 4;
    float4 v = *(const float4*)(X + i);
    __half2 p0 = __floats2half2_rn(v.x, v.y);
    __half2 p1 = __floats2half2_rn(v.z, v.w);
    *(uint2*)(O + i) = make_uint2(*(uint32_t*)&p0, *(uint32_t*)&p1);
}

// ==== f16 proj GEMM core: 128B K-chunks, 2-stage cp.async (3 CTAs/SM) ======
__device__ __forceinline__ void gemm_tile_f16(const char* Ag, const char* Wg,
                                              uint32_t s0,
                                              uint32_t (&acc)[2][8][2],
                                              int tid, int lane, int warp_m, int warp_n) {
    const int q = lane >> 3, rr = lane & 7;
    const uint32_t lds_off = (uint32_t)(((q & 1) * 8 + rr) * LDW + (q >> 1) * 16);
    const uint32_t am_off = (uint32_t)(warp_m * 32) * LDW + lds_off;
    const uint32_t bn_off = 128u * LDW + (uint32_t)(warp_n * 64) * LDW + lds_off;

    auto load_chunk = [&](int kc, int stg) {
        const uint32_t b = s0 + stg * GSTG;
#pragma unroll
        for (int it = 0; it < 8; it++) {
            const int u = it * 256 + tid;
            const int m = u >> 10;
            const int row = (u >> 3) & 127;
            const int g = u & 7;
            const char* src = (m ? Wg : Ag) + (size_t)row * (DDIM * 2)
                              + (size_t)kc * 128 + g * 16;
            CP16(b + (uint32_t)m * (128u * LDW) + (uint32_t)row * LDW + g * 16, src);
        }
        CPCOMMIT();
    };

    load_chunk(0, 0);
    for (int kc = 0; kc < 8; kc++) {
        if (kc + 1 < 8) load_chunk(kc + 1, (kc + 1) & 1);
        if (kc < 7) { CPWAIT(1); } else { CPWAIT(0); }
        __syncthreads();
        const uint32_t b = s0 + (kc & 1) * GSTG;
        const uint32_t a_base = b + am_off;
        const uint32_t b_base = b + bn_off;
#pragma unroll
        for (int kk = 0; kk < 4; kk++) {
            uint32_t af[2][4];
            ldsm_x4(af[0], a_base + kk * 32);
            ldsm_x4(af[1], a_base + 16 * LDW + kk * 32);
#pragma unroll
            for (int n2 = 0; n2 < 4; n2++) {
                uint32_t bf[4];
                ldsm_x4(bf, b_base + n2 * 16 * LDW + kk * 32);
#pragma unroll
                for (int mt = 0; mt < 2; mt++)
#pragma unroll
                    for (int u = 0; u < 2; u++)
                        mma16816h(acc[mt][n2 * 2 + u], af[mt], bf[u], bf[u + 2]);
            }
        }
        __syncthreads();   // all warps done reading before next load overwrites
    }
}

// ============ f16 projection GEMM (z-batched over embeddings) ===============
template <bool DO_ELU>
__global__ void __launch_bounds__(256, 3)
proj_kernel(const __half* __restrict__ A, const __half* __restrict__ W,
            const float* __restrict__ bias, __half* __restrict__ Oh) {
    extern __shared__ __align__(128) char dynsm[];
    const int tid = threadIdx.x, lane = tid & 31, wid = tid >> 5;
    const int warp_m = wid & 3, warp_n = wid >> 2;
    const int cb = blockIdx.x, rb = blockIdx.y;
    const size_t zoff = (size_t)blockIdx.z * ZSTRIDE;

    uint32_t acc[2][8][2] = {};
    gemm_tile_f16((const char*)(A + zoff + (size_t)rb * TS * DDIM),
                  (const char*)(W + (size_t)cb * TS * DDIM),
                  smem_u32(dynsm), acc, tid, lane, warp_m, warp_n);

    const int cbase = cb * TS + warp_n * 64;
    const int rbase = rb * TS + warp_m * 32 + (lane >> 2);
#pragma unroll
    for (int mt = 0; mt < 2; mt++) {
        const int ra = rbase + mt * 16, rbb = ra + 8;
#pragma unroll
        for (int nt = 0; nt < 8; nt++) {
            const int c = cbase + nt * 8 + (lane & 3) * 2;
            const float bv0 = bias[c], bv1 = bias[c + 1];
            float2 f01 = __half22float2(*(__half2*)&acc[mt][nt][0]);
            float2 f23 = __half22float2(*(__half2*)&acc[mt][nt][1]);
            float x00 = f01.x + bv0, x01 = f01.y + bv1;
            float x10 = f23.x + bv0, x11 = f23.y + bv1;
            if (DO_ELU) {
                x00 = (x00 > 0.0f) ? x00 : expm1f(x00);
                x01 = (x01 > 0.0f) ? x01 : expm1f(x01);
                x10 = (x10 > 0.0f) ? x10 : expm1f(x10);
                x11 = (x11 > 0.0f) ? x11 : expm1f(x11);
            }
            __half2 p = __floats2half2_rn(x00, x01);
            __half2 q2 = __floats2half2_rn(x10, x11);
            *(uint32_t*)(Oh + zoff + (size_t)ra  * DDIM + c) = *(uint32_t*)&p;
            *(uint32_t*)(Oh + zoff + (size_t)rbb * DDIM + c) = *(uint32_t*)&q2;
        }
    }
}

// ======= similarity tile core (fp8, f16 acc, 128B chunks, 3 stages) ========
__device__ __forceinline__ void sim_tile_mma_fp8(const char* Ag, const char* Bg,
                                                 uint32_t s0,
                                                 uint32_t (&acc)[2][8][2],
                                                 int tid, int lane, int warp_m, int warp_n) {
    const int q = lane >> 3, rr = lane & 7;
    const uint32_t lds_off = (uint32_t)(((q & 1) * 8 + rr) * LDW + (q >> 1) * 16);
    const uint32_t am_off = (uint32_t)(warp_m * 32) * LDW + lds_off;
    const uint32_t bn_off = 128u * LDW + (uint32_t)(warp_n * 64) * LDW + lds_off;

    auto load_chunk = [&](int kc, int stg) {
        const uint32_t b = s0 + stg * GSTG;
#pragma unroll
        for (int it = 0; it < 8; it++) {
            const int u = it * 256 + tid;
            const int m = u >> 10;
            const int row = (u >> 3) & 127;
            const int g = u & 7;
            const char* src = (m ? Bg : Ag) + (size_t)row * DDIM
                              + (size_t)kc * 128 + g * 16;
            CP16(b + (uint32_t)m * (128u * LDW) + (uint32_t)row * LDW + g * 16, src);
        }
        CPCOMMIT();
    };

    load_chunk(0, 0);
    load_chunk(1, 1);
    int cur = 0;
    for (int kc = 0; kc < 4; kc++) {
        if (kc < 3) { CPWAIT(1); } else { CPWAIT(0); }
        __syncthreads();
        if (kc + 2 < 4) {
            int iss = cur + 2; if (iss >= 3) iss -= 3;
            load_chunk(kc + 2, iss);
        }
        const uint32_t b = s0 + cur * GSTG;
        const uint32_t a_base = b + am_off;
        const uint32_t b_base = b + bn_off;
#pragma unroll
        for (int kk = 0; kk < 4; kk++) {
            uint32_t af[2][4];
            ldsm_x4(af[0], a_base + kk * 32);
            ldsm_x4(af[1], a_base + 16 * LDW + kk * 32);
#pragma unroll
            for (int n2 = 0; n2 < 4; n2++) {
                uint32_t bf[4];
                ldsm_x4(bf, b_base + n2 * 16 * LDW + kk * 32);
#pragma unroll
                for (int mt = 0; mt < 2; mt++)
#pragma unroll
                    for (int u = 0; u < 2; u++)
                        mma16832_fp8h(acc[mt][n2 * 2 + u], af[mt], bf[u], bf[u + 2]);
            }
        }
        cur = (cur + 1 == 3) ? 0 : cur + 1;
    }
    __syncthreads();
}

// exp + row/col reductions (acc halves hold dot * 256)
__device__ __forceinline__ void sim_reduce(uint32_t (&acc)[2][8][2], char* sm,
                                           int lane, int warp_m, int warp_n,
                                           bool do_col) {
    float* rs_sm = (float*)sm;
    float* cs_sm = (float*)(sm + 1024);
    const float C = 2.8853900817779268f / (FP8SCALE * FP8SCALE);
    float rs_acc[2][2] = {};
    float cs2[8][2];
    if (do_col)
#pragma unroll
        for (int nt = 0; nt < 8; nt++) cs2[nt][0] = cs2[nt][1] = 0.0f;

#pragma unroll
    for (int mt = 0; mt < 2; mt++)
#pragma unroll
        for (int nt = 0; nt < 8; nt++) {
            float2 f01 = __half22float2(*(__half2*)&acc[mt][nt][0]);
            float2 f23 = __half22float2(*(__half2*)&acc[mt][nt][1]);
            float e0 = fast_exp2(f01.x * C);
            float e1 = fast_exp2(f01.y * C);
            float e2 = fast_exp2(f23.x * C);
            float e3 = fast_exp2(f23.y * C);
            rs_acc[mt][0] += e0 + e1;
            rs_acc[mt][1] += e2 + e3;
            if (do_col) { cs2[nt][0] += e0 + e2; cs2[nt][1] += e1 + e3; }
        }

#pragma unroll
    for (int mt = 0; mt < 2; mt++)
#pragma unroll
        for (int half = 0; half < 2; half++) {
            float v = rs_acc[mt][half];
            v += __shfl_xor_sync(0xffffffffu, v, 1);
            v += __shfl_xor_sync(0xffffffffu, v, 2);
            if ((lane & 3) == 0) {
                int row = warp_m * 32 + mt * 16 + half * 8 + (lane >> 2);
                rs_sm[row * 2 + warp_n] = v;
            }
        }
    if (do_col) {
#pragma unroll
        for (int nt = 0; nt < 8; nt++)
#pragma unroll
            for (int e = 0; e < 2; e++) {
                float v = cs2[nt][e];
                v += __shfl_xor_sync(0xffffffffu, v, 4);
                v += __shfl_xor_sync(0xffffffffu, v, 8);
                v += __shfl_xor_sync(0xffffffffu, v, 16);
                if (lane < 4) {
                    int col = warp_n * 64 + nt * 8 + lane * 2 + e;
                    cs_sm[warp_m * 128 + col] = v;
                }
            }
    }
    __syncthreads();
}

// ============ unified similarity kernel: all 8256 tiles in ONE launch =======
__global__ void __launch_bounds__(256, 2)
sim_all_kernel(const uint8_t* __restrict__ F1, const uint8_t* __restrict__ F2,
               float* __restrict__ rs11p, float* __restrict__ rs22p,
               float* __restrict__ rs12p, float* __restrict__ cs12p) {
    extern __shared__ __align__(128) char dynsm[];
    const int bid = blockIdx.x;
    const int tid = threadIdx.x, lane = tid & 31, wid = tid >> 5;
    const int warp_m = wid & 3, warp_n = wid >> 2;

    const uint8_t *A, *B;
    float *rsp, *csp;
    int rb, cb;
    bool diag = false, sym;

    if (bid < 2 * NSYM) {
        sym = true;
        const int z = (bid >= NSYM) ? 1 : 0;
        const int idx = bid - z * NSYM;
        int r = (int)(NBLK + 0.5f - sqrtf((NBLK + 0.5f) * (NBLK + 0.5f) - 2.0f * idx));
        if (r < 0) r = 0;
        if (r > NBLK - 1) r = NBLK - 1;
#define TRI_BASE(x) ((x) * NBLK - ((x) * ((x) - 1)) / 2)
        while (r + 1 <= NBLK - 1 && TRI_BASE(r + 1) <= idx) r++;
        while (r > 0 && TRI_BASE(r) > idx) r--;
        rb = r;
        cb = r + (idx - TRI_BASE(r));
#undef TRI_BASE
        A = z ? F2 : F1;
        B = A;
        rsp = z ? rs22p : rs11p;
        csp = nullptr;
        diag = (rb == cb);
    } else {
        sym = false;
        const int idx = bid - 2 * NSYM;
        rb = idx >> 6;
        cb = idx & (NBLK - 1);
        A = F1; B = F2;
        rsp = rs12p; csp = cs12p;
    }

    uint32_t acc[2][8][2] = {};
    sim_tile_mma_fp8((const char*)(A + (size_t)rb * TS * DDIM),
                     (const char*)(B + (size_t)cb * TS * DDIM),
                     smem_u32(dynsm), acc, tid, lane, warp_m, warp_n);
    sim_reduce(acc, dynsm, lane, warp_m, warp_n, !diag);

    float* rs_sm = (float*)dynsm;
    float* cs_sm = (float*)(dynsm + 1024);
    if (tid < TS) {
        rsp[(size_t)(rb * TS + tid) * NBLK + cb] = rs_sm[tid * 2] + rs_sm[tid * 2 + 1];
        if (!diag) {
            const float ctot = cs_sm[tid] + cs_sm[128 + tid] +
                               cs_sm[256 + tid] + cs_sm[384 + tid];
            if (sym) rsp[(size_t)(cb * TS + tid) * NBLK + rb] = ctot;
            else     csp[(size_t)(cb * TS + tid) * NBLK + rb] = ctot;
        }
    }
}

// ------- fused: L2-normalize both embeddings (f16 in), d12, fp8 out --------
__global__ void __launch_bounds__(256)
normd12_kernel(const __half* __restrict__ Hh, uint8_t* __restrict__ F1,
               uint8_t* __restrict__ F2, float* __restrict__ d12) {
    const int row  = blockIdx.x * 8 + (threadIdx.x >> 5);
    const int lane = threadIdx.x & 31;
    const uint4* h1 = (const uint4*)(Hh + (size_t)row * DDIM);
    const uint4* h2 = (const uint4*)(Hh + ZSTRIDE + (size_t)row * DDIM);
    float a1[16], a2[16];
    float ss1 = 0.0f, ss2 = 0.0f, dd = 0.0f;
#pragma unroll
    for (int m = 0; m < 2; m++) {
        uint4 u = h1[lane + 32 * m];
        uint4 w = h2[lane + 32 * m];
        const uint32_t up[4] = {u.x, u.y, u.z, u.w};
        const uint32_t wp[4] = {w.x, w.y, w.z, w.w};
#pragma unroll
        for (int k = 0; k < 4; k++) {
            float2 f1 = __half22float2(*(__half2*)&up[k]);
            float2 f2 = __half22float2(*(__half2*)&wp[k]);
            a1[m * 8 + k * 2]     = f1.x;
            a1[m * 8 + k * 2 + 1] = f1.y;
            a2[m * 8 + k * 2]     = f2.x;
            a2[m * 8 + k * 2 + 1] = f2.y;
            ss1 += f1.x * f1.x + f1.y * f1.y;
            ss2 += f2.x * f2.x + f2.y * f2.y;
            dd  += f1.x * f2.x + f1.y * f2.y;
        }
    }
#pragma unroll
    for (int o = 16; o > 0; o >>= 1) {
        ss1 += __shfl_xor_sync(0xffffffffu, ss1, o);
        ss2 += __shfl_xor_sync(0xffffffffu, ss2, o);
        dd  += __shfl_xor_sync(0xffffffffu, dd,  o);
    }
    const float inv1 = 1.0f / fmaxf(sqrtf(ss1), 1e-12f);
    const float inv2 = 1.0f / fmaxf(sqrtf(ss2), 1e-12f);
    const float s1 = inv1 * FP8SCALE, s2 = inv2 * FP8SCALE;
#pragma unroll
    for (int m = 0; m < 2; m++)
#pragma unroll
        for (int k = 0; k < 2; k++) {
            const int e = m * 8 + k * 4;
            __nv_fp8x2_storage_t lo1 = __nv_cvt_float2_to_fp8x2(
                make_float2(a1[e] * s1, a1[e + 1] * s1), __NV_SATFINITE, __NV_E4M3);
            __nv_fp8x2_storage_t hi1 = __nv_cvt_float2_to_fp8x2(
                make_float2(a1[e + 2] * s1, a1[e + 3] * s1), __NV_SATFINITE, __NV_E4M3);
            *(uint32_t*)(F1 + (size_t)row * DDIM + (lane + 32 * m) * 8 + k * 4) =
                (uint32_t)lo1 | ((uint32_t)hi1 << 16);
            __nv_fp8x2_storage_t lo2 = __nv_cvt_float2_to_fp8x2(
                make_float2(a2[e] * s2, a2[e + 1] * s2), __NV_SATFINITE, __NV_E4M3);
            __nv_fp8x2_storage_t hi2 = __nv_cvt_float2_to_fp8x2(
                make_float2(a2[e + 2] * s2, a2[e + 3] * s2), __NV_SATFINITE, __NV_E4M3);
            *(uint32_t*)(F2 + (size_t)row * DDIM + (lane + 32 * m) * 8 + k * 4) =
                (uint32_t)lo2 | ((uint32_t)hi2 << 16);
        }
    if (lane == 0) d12[row] = dd * inv1 * inv2;
}

__global__ void __launch_bounds__(256)
rowloss_kernel(const float* __restrict__ rs11p, const float* __restrict__ rs22p,
               const float* __restrict__ rs12p, const float* __restrict__ cs12p,
               const float* __restrict__ d12, float* __restrict__ loss) {
    const int row  = blockIdx.x * 8 + (threadIdx.x >> 5);
    const int lane = threadIdx.x & 31;
    float s11 = 0.0f, s22 = 0.0f, s12 = 0.0f, c12 = 0.0f;
    for (int m = lane; m < NBLK; m += 32) {
        const size_t o = (size_t)row * NBLK + m;
        s11 += rs11p[o];
        s22 += rs22p[o];
        s12 += rs12p[o];
        c12 += cs12p[o];
    }
#pragma unroll
    for (int o = 16; o > 0; o >>= 1) {
        s11 += __shfl_xor_sync(0xffffffffu, s11, o);
        s22 += __shfl_xor_sync(0xffffffffu, s22, o);
        s12 += __shfl_xor_sync(0xffffffffu, s12, o);
        c12 += __shfl_xor_sync(0xffffffffu, c12, o);
    }
    if (lane == 0) {
        const float E2 = 7.38905609893065f;   // exp(1/tau)
        const float den1 = s11 + s12 - E2;
        const float den2 = s22 + c12 - E2;
        loss[row] = -2.0f * d12[row] + 0.5f * (__logf(den1) + __logf(den2));
    }
}

__global__ void __launch_bounds__(1024)
final_kernel(const float* __restrict__ loss, float* __restrict__ out) {
    __shared__ float sm[1024];
    const int t = threadIdx.x;
    float s = 0.0f;
    for (int i = t; i < NROWS; i += 1024) s += loss[i];
    sm[t] = s;
    __syncthreads();
    for (int o = 512; o > 0; o >>= 1) {
        if (t < o) sm[t] += sm[t + o];
        __syncthreads();
    }
    if (t == 0) out[0] = sm[0] * (1.0f / NROWS);
}

// ---------------- launch ----------------------------------------------------
extern "C" void kernel_launch(void* const* d_in, const int* in_sizes, int n_in,
                              void* d_out, int out_size) {
    const float* pri = (const float*)d_in[0];
    const float* aux = (const float*)d_in[1];
    const float* W1  = (const float*)d_in[2];
    const float* b1  = (const float*)d_in[3];
    const float* W2  = (const float*)d_in[4];
    const float* b2  = (const float*)d_in[5];
    float* out = (float*)d_out;

    __half *Zh, *Th, *Wh, *Hh;
    uint8_t *F1, *F2;
    float *rs11p, *rs22p, *rs12p, *cs12p, *d12, *loss;
    cudaGetSymbolAddress((void**)&Zh,  g_Zh);
    cudaGetSymbolAddress((void**)&Th,  g_Th);
    cudaGetSymbolAddress((void**)&Wh,  g_Wh);
    cudaGetSymbolAddress((void**)&Hh,  g_Hh);
    cudaGetSymbolAddress((void**)&F1,  g_F1);
    cudaGetSymbolAddress((void**)&F2,  g_F2);
    cudaGetSymbolAddress((void**)&rs11p, g_rs11p);
    cudaGetSymbolAddress((void**)&rs22p, g_rs22p);
    cudaGetSymbolAddress((void**)&rs12p, g_rs12p);
    cudaGetSymbolAddress((void**)&cs12p, g_cs12p);
    cudaGetSymbolAddress((void**)&d12,  g_d12);
    cudaGetSymbolAddress((void**)&loss, g_loss);

    const int simSmem  = 3 * GSTG;   // 110592, 2 CTAs/SM
    const int projSmem = 2 * GSTG;   // 73728,  3 CTAs/SM
    cudaFuncSetAttribute(proj_kernel<true >,
                         cudaFuncAttributeMaxDynamicSharedMemorySize, projSmem);
    cudaFuncSetAttribute(proj_kernel<false>,
                         cudaFuncAttributeMaxDynamicSharedMemorySize, projSmem);
    cudaFuncSetAttribute(sim_all_kernel,
                         cudaFuncAttributeMaxDynamicSharedMemorySize, simSmem);

    const dim3 pg(DDIM / TS, NROWS / TS, 2);        // (4, 64, 2)
    const int simBlocks = 2 * NSYM + NBLK * NBLK;   // 8256
    const int cvtBlocks = 512 + 2 * (NROWS * DDIM / 1024);   // 8704

    convert_kernel<<<cvtBlocks, 256>>>(W1, W2, pri, aux, Wh, Zh);

    proj_kernel<true ><<<pg, 256, projSmem>>>(Zh, Wh, b1, Th);
    proj_kernel<false><<<pg, 256, projSmem>>>(Th, Wh + (size_t)DDIM * DDIM, b2, Hh);

    normd12_kernel<<<NROWS / 8, 256>>>(Hh, F1, F2, d12);

    sim_all_kernel<<<simBlocks, 256, simSmem>>>(F1, F2, rs11p, rs22p, rs12p, cs12p);

    rowloss_kernel<<<NROWS / 8, 256>>>(rs11p, rs22p, rs12p, cs12p, d12, loss);
    final_kernel<<<1, 1024>>>(loss, out);
}